// round 8
// baseline (speedup 1.0000x reference)
#include <cuda_runtime.h>
#include <stdint.h>

#define S_LEN 4096
#define DM    768
#define NH    12
#define HD    64

// Scratch (no cudaMalloc allowed)
__device__ float g_q[S_LEN * DM];
__device__ float g_k[S_LEN * DM];
__device__ float g_v[S_LEN * DM];
__device__ float g_att[S_LEN * DM];

__device__ __forceinline__ uint32_t f2tf(float x) {
    uint32_t r;
    asm("cvt.rna.tf32.f32 %0, %1;" : "=r"(r) : "f"(x));
    return r;
}

__device__ __forceinline__ void mma_tf32(float c[4],
    uint32_t a0, uint32_t a1, uint32_t a2, uint32_t a3,
    uint32_t b0, uint32_t b1)
{
    asm volatile(
        "mma.sync.aligned.m16n8k8.row.col.f32.tf32.tf32.f32 "
        "{%0,%1,%2,%3}, {%4,%5,%6,%7}, {%8,%9}, {%0,%1,%2,%3};"
        : "+f"(c[0]), "+f"(c[1]), "+f"(c[2]), "+f"(c[3])
        : "r"(a0), "r"(a1), "r"(a2), "r"(a3), "r"(b0), "r"(b1));
}

#define AST 36
#define BST 72

// ---------------------------------------------------------------------------
// Projection GEMM: block tile 256x64, 128 thr = 4 warps x (64m x 64n).
// mt=4, nt=8 -> 1.0 LDS/mma (B-frags amortized over 4 m-tiles).
// ---------------------------------------------------------------------------
__device__ __forceinline__ void gemm_body256(
    const float* __restrict__ A, const float* __restrict__ B,
    float* __restrict__ C, int N, int K, int bx, int by)
{
    __shared__ uint32_t As[256 * AST];   // 36864 B
    __shared__ uint32_t Bs[32 * BST];    //  9216 B

    const int tid  = threadIdx.x;
    const int warp = tid >> 5, lane = tid & 31;
    const int g = lane >> 2, tg = lane & 3;
    const int m0 = by * 256, n0 = bx * 64;
    const int wbase = warp * 64;

    float acc[4][8][4];
#pragma unroll
    for (int mt = 0; mt < 4; mt++)
#pragma unroll
        for (int nt = 0; nt < 8; nt++)
#pragma unroll
            for (int c = 0; c < 4; c++) acc[mt][nt][c] = 0.f;

    float4 ra[16], rb[4];
#pragma unroll
    for (int it = 0; it < 16; it++) {
        int idx = it * 128 + tid;
        int r = idx >> 3, c4 = (idx & 7) * 4;
        ra[it] = *(const float4*)&A[(size_t)(m0 + r) * K + c4];
    }
#pragma unroll
    for (int it = 0; it < 4; it++) {
        int idx = it * 128 + tid;
        int r = idx >> 4, c4 = (idx & 15) * 4;
        rb[it] = *(const float4*)&B[(size_t)r * N + n0 + c4];
    }

    for (int k0 = 0; k0 < K; k0 += 32) {
        // stage current tile (tf32 in SMEM)
#pragma unroll
        for (int it = 0; it < 16; it++) {
            int idx = it * 128 + tid;
            int r = idx >> 3, c4 = (idx & 7) * 4;
            *(uint4*)&As[r * AST + c4] =
                make_uint4(f2tf(ra[it].x), f2tf(ra[it].y), f2tf(ra[it].z), f2tf(ra[it].w));
        }
#pragma unroll
        for (int it = 0; it < 4; it++) {
            int idx = it * 128 + tid;
            int r = idx >> 4, c4 = (idx & 15) * 4;
            *(uint4*)&Bs[r * BST + c4] =
                make_uint4(f2tf(rb[it].x), f2tf(rb[it].y), f2tf(rb[it].z), f2tf(rb[it].w));
        }
        __syncthreads();

        // prefetch next tile (hidden behind mma loop)
        if (k0 + 32 < K) {
#pragma unroll
            for (int it = 0; it < 16; it++) {
                int idx = it * 128 + tid;
                int r = idx >> 3, c4 = (idx & 7) * 4;
                ra[it] = *(const float4*)&A[(size_t)(m0 + r) * K + k0 + 32 + c4];
            }
#pragma unroll
            for (int it = 0; it < 4; it++) {
                int idx = it * 128 + tid;
                int r = idx >> 4, c4 = (idx & 15) * 4;
                rb[it] = *(const float4*)&B[(size_t)(k0 + 32 + r) * N + n0 + c4];
            }
        }

#pragma unroll
        for (int kk = 0; kk < 4; kk++) {
            int kc = kk * 8 + tg;
            uint32_t a[4][4];
#pragma unroll
            for (int mt = 0; mt < 4; mt++) {
                int r = wbase + mt * 16 + g;
                a[mt][0] = As[r * AST + kc];
                a[mt][1] = As[(r + 8) * AST + kc];
                a[mt][2] = As[r * AST + kc + 4];
                a[mt][3] = As[(r + 8) * AST + kc + 4];
            }
#pragma unroll
            for (int nt = 0; nt < 8; nt++) {
                int c = nt * 8 + g;
                uint32_t b0 = Bs[kc * BST + c];
                uint32_t b1 = Bs[(kc + 4) * BST + c];
#pragma unroll
                for (int mt = 0; mt < 4; mt++)
                    mma_tf32(acc[mt][nt], a[mt][0], a[mt][1], a[mt][2], a[mt][3], b0, b1);
            }
        }
        __syncthreads();
    }

#pragma unroll
    for (int mt = 0; mt < 4; mt++) {
#pragma unroll
        for (int nt = 0; nt < 8; nt++) {
            int r = m0 + wbase + mt * 16 + g;
            int c = n0 + nt * 8 + 2 * tg;
            *(float2*)&C[(size_t)r * N + c] =
                make_float2(acc[mt][nt][0], acc[mt][nt][1]);
            *(float2*)&C[(size_t)(r + 8) * N + c] =
                make_float2(acc[mt][nt][2], acc[mt][nt][3]);
        }
    }
}

__global__ __launch_bounds__(128) void proj3_mma(
    const float* __restrict__ Q, const float* __restrict__ K,
    const float* __restrict__ V,
    const float* __restrict__ Wq, const float* __restrict__ Wk,
    const float* __restrict__ Wv,
    float* __restrict__ gq, float* __restrict__ gk, float* __restrict__ gv)
{
    const float* A;
    const float* B;
    float* C;
    if (blockIdx.z == 0)      { A = Q; B = Wq; C = gq; }
    else if (blockIdx.z == 1) { A = K; B = Wk; C = gk; }
    else                      { A = V; B = Wv; C = gv; }
    gemm_body256(A, B, C, DM, DM, blockIdx.x, blockIdx.y);
}

// ---------------------------------------------------------------------------
// Output GEMM: round-7 shape (128x64 tile, 384 blocks - good wave balance).
// ---------------------------------------------------------------------------
__global__ __launch_bounds__(128) void gemm_bias_mma(
    const float* __restrict__ A, const float* __restrict__ B,
    const float* __restrict__ bias, float* __restrict__ C)
{
    __shared__ uint32_t As[128 * AST];
    __shared__ uint32_t Bs[32 * BST];

    const int N = DM, K = DM;
    const int tid  = threadIdx.x;
    const int warp = tid >> 5, lane = tid & 31;
    const int g = lane >> 2, tg = lane & 3;
    const int m0 = blockIdx.y * 128, n0 = blockIdx.x * 64;
    const int wbase = warp * 32;

    float acc[2][8][4];
#pragma unroll
    for (int mt = 0; mt < 2; mt++)
#pragma unroll
        for (int nt = 0; nt < 8; nt++)
#pragma unroll
            for (int c = 0; c < 4; c++) acc[mt][nt][c] = 0.f;

    float4 ra[8], rb[4];
#pragma unroll
    for (int it = 0; it < 8; it++) {
        int idx = it * 128 + tid;
        int r = idx >> 3, c4 = (idx & 7) * 4;
        ra[it] = *(const float4*)&A[(size_t)(m0 + r) * K + c4];
    }
#pragma unroll
    for (int it = 0; it < 4; it++) {
        int idx = it * 128 + tid;
        int r = idx >> 4, c4 = (idx & 15) * 4;
        rb[it] = *(const float4*)&B[(size_t)r * N + n0 + c4];
    }

    for (int k0 = 0; k0 < K; k0 += 32) {
#pragma unroll
        for (int it = 0; it < 8; it++) {
            int idx = it * 128 + tid;
            int r = idx >> 3, c4 = (idx & 7) * 4;
            *(uint4*)&As[r * AST + c4] =
                make_uint4(f2tf(ra[it].x), f2tf(ra[it].y), f2tf(ra[it].z), f2tf(ra[it].w));
        }
#pragma unroll
        for (int it = 0; it < 4; it++) {
            int idx = it * 128 + tid;
            int r = idx >> 4, c4 = (idx & 15) * 4;
            *(uint4*)&Bs[r * BST + c4] =
                make_uint4(f2tf(rb[it].x), f2tf(rb[it].y), f2tf(rb[it].z), f2tf(rb[it].w));
        }
        __syncthreads();

        if (k0 + 32 < K) {
#pragma unroll
            for (int it = 0; it < 8; it++) {
                int idx = it * 128 + tid;
                int r = idx >> 3, c4 = (idx & 7) * 4;
                ra[it] = *(const float4*)&A[(size_t)(m0 + r) * K + k0 + 32 + c4];
            }
#pragma unroll
            for (int it = 0; it < 4; it++) {
                int idx = it * 128 + tid;
                int r = idx >> 4, c4 = (idx & 15) * 4;
                rb[it] = *(const float4*)&B[(size_t)(k0 + 32 + r) * N + n0 + c4];
            }
        }

#pragma unroll
        for (int kk = 0; kk < 4; kk++) {
            int kc = kk * 8 + tg;
            uint32_t a[2][4];
#pragma unroll
            for (int mt = 0; mt < 2; mt++) {
                int r = wbase + mt * 16 + g;
                a[mt][0] = As[r * AST + kc];
                a[mt][1] = As[(r + 8) * AST + kc];
                a[mt][2] = As[r * AST + kc + 4];
                a[mt][3] = As[(r + 8) * AST + kc + 4];
            }
#pragma unroll
            for (int nt = 0; nt < 8; nt++) {
                int c = nt * 8 + g;
                uint32_t b0 = Bs[kc * BST + c];
                uint32_t b1 = Bs[(kc + 4) * BST + c];
                mma_tf32(acc[0][nt], a[0][0], a[0][1], a[0][2], a[0][3], b0, b1);
                mma_tf32(acc[1][nt], a[1][0], a[1][1], a[1][2], a[1][3], b0, b1);
            }
        }
        __syncthreads();
    }

#pragma unroll
    for (int mt = 0; mt < 2; mt++) {
#pragma unroll
        for (int nt = 0; nt < 8; nt++) {
            int r = m0 + wbase + mt * 16 + g;
            int c = n0 + nt * 8 + 2 * tg;
            float b0 = bias[c], b1 = bias[c + 1];
            *(float2*)&C[(size_t)r * N + c] =
                make_float2(acc[mt][nt][0] + b0, acc[mt][nt][1] + b1);
            *(float2*)&C[(size_t)(r + 8) * N + c] =
                make_float2(acc[mt][nt][2] + b0, acc[mt][nt][3] + b1);
        }
    }
}

// ---------------------------------------------------------------------------
// Flash attention: byte-identical to round 6/7 (known good, 285us).
// ---------------------------------------------------------------------------
#define QST 68
#define KST 68
#define VST 72
#define PST 68
#define ATTN_SMEM ((128*QST + 64*KST + 64*VST + 128*PST) * 4)  // 105472 B

__global__ __launch_bounds__(128, 2) void attn_mma(
    const float* __restrict__ q, const float* __restrict__ k,
    const float* __restrict__ v, float* __restrict__ o)
{
    extern __shared__ uint32_t sm[];
    uint32_t* Qs = sm;
    uint32_t* Ks = Qs + 128 * QST;
    uint32_t* Vs = Ks + 64 * KST;
    uint32_t* Ps = Vs + 64 * VST;

    const int h = blockIdx.y;
    const int t = blockIdx.x;
    const int iq = (t & 1) ? (31 - (t >> 1)) : (t >> 1);
    const int tid = threadIdx.x, warp = tid >> 5, lane = tid & 31;
    const int g = lane >> 2, tg = lane & 3;
    const size_t hoff = (size_t)h * HD;
    const int wbase = warp * 32;
    const int qrow0 = iq * 128 + wbase + g;

    const int skey = tid >> 4;
    const int sd4  = (tid & 15) * 4;

#pragma unroll
    for (int it = 0; it < 16; it++) {
        int idx = it * 128 + tid;
        int r = idx >> 4, d4 = (idx & 15) * 4;
        float4 val = *(const float4*)&q[(size_t)(iq * 128 + r) * DM + hoff + d4];
        *(uint4*)&Qs[r * QST + d4] =
            make_uint4(f2tf(val.x), f2tf(val.y), f2tf(val.z), f2tf(val.w));
    }

    float of[2][8][4];
#pragma unroll
    for (int mt = 0; mt < 2; mt++)
#pragma unroll
        for (int nt = 0; nt < 8; nt++)
#pragma unroll
            for (int c = 0; c < 4; c++) of[mt][nt][c] = 0.f;
    float mrow[2][2], lrow[2][2];
#pragma unroll
    for (int mt = 0; mt < 2; mt++) {
        mrow[mt][0] = mrow[mt][1] = -1e30f;
        lrow[mt][0] = lrow[mt][1] = 0.f;
    }

    float4 pk[8], pv[8];
#pragma unroll
    for (int it = 0; it < 8; it++) {
        size_t gidx = hoff + (size_t)(it * 8 + skey) * DM + sd4;
        pk[it] = *(const float4*)&k[gidx];
        pv[it] = *(const float4*)&v[gidx];
    }

    __syncthreads();

    const int ktmax = 2 * iq + 1;
    for (int kt = 0; kt <= ktmax; kt++) {
#pragma unroll
        for (int it = 0; it < 8; it++) {
            int key = it * 8 + skey;
            *(uint4*)&Ks[key * KST + sd4] =
                make_uint4(f2tf(pk[it].x), f2tf(pk[it].y), f2tf(pk[it].z), f2tf(pk[it].w));
            *(uint4*)&Vs[key * VST + sd4] =
                make_uint4(f2tf(pv[it].x), f2tf(pv[it].y), f2tf(pv[it].z), f2tf(pv[it].w));
        }
        __syncthreads();

        float s[2][8][4];
#pragma unroll
        for (int mt = 0; mt < 2; mt++)
#pragma unroll
            for (int nt = 0; nt < 8; nt++)
#pragma unroll
                for (int c = 0; c < 4; c++) s[mt][nt][c] = 0.f;

#pragma unroll
        for (int ks = 0; ks < 8; ks++) {
            int kc = ks * 8 + tg;
            uint32_t a[2][4];
#pragma unroll
            for (int mt = 0; mt < 2; mt++) {
                int wr = wbase + mt * 16 + g;
                a[mt][0] = Qs[wr * QST + kc];
                a[mt][1] = Qs[(wr + 8) * QST + kc];
                a[mt][2] = Qs[wr * QST + kc + 4];
                a[mt][3] = Qs[(wr + 8) * QST + kc + 4];
            }
#pragma unroll
            for (int nt = 0; nt < 8; nt++) {
                uint32_t b0 = Ks[(nt * 8 + g) * KST + kc];
                uint32_t b1 = Ks[(nt * 8 + g) * KST + kc + 4];
                mma_tf32(s[0][nt], a[0][0], a[0][1], a[0][2], a[0][3], b0, b1);
                mma_tf32(s[1][nt], a[1][0], a[1][1], a[1][2], a[1][3], b0, b1);
            }
        }

        const bool need_mask = (kt >= 2 * iq);
#pragma unroll
        for (int mt = 0; mt < 2; mt++) {
            int r0 = qrow0 + mt * 16;
#pragma unroll
            for (int nt = 0; nt < 8; nt++) {
                s[mt][nt][0] *= 0.125f; s[mt][nt][1] *= 0.125f;
                s[mt][nt][2] *= 0.125f; s[mt][nt][3] *= 0.125f;
                if (need_mask) {
                    int col = kt * 64 + nt * 8 + 2 * tg;
                    if (col     > r0)     s[mt][nt][0] = -1e30f;
                    if (col + 1 > r0)     s[mt][nt][1] = -1e30f;
                    if (col     > r0 + 8) s[mt][nt][2] = -1e30f;
                    if (col + 1 > r0 + 8) s[mt][nt][3] = -1e30f;
                }
            }
        }

#pragma unroll
        for (int mt = 0; mt < 2; mt++) {
            float rm0 = -1e30f, rm1 = -1e30f;
#pragma unroll
            for (int nt = 0; nt < 8; nt++) {
                rm0 = fmaxf(rm0, fmaxf(s[mt][nt][0], s[mt][nt][1]));
                rm1 = fmaxf(rm1, fmaxf(s[mt][nt][2], s[mt][nt][3]));
            }
#pragma unroll
            for (int off = 1; off <= 2; off <<= 1) {
                rm0 = fmaxf(rm0, __shfl_xor_sync(0xFFFFFFFFu, rm0, off));
                rm1 = fmaxf(rm1, __shfl_xor_sync(0xFFFFFFFFu, rm1, off));
            }
            float nm0 = fmaxf(mrow[mt][0], rm0), nm1 = fmaxf(mrow[mt][1], rm1);
            float al0 = __expf(mrow[mt][0] - nm0), al1 = __expf(mrow[mt][1] - nm1);
            float sum0 = 0.f, sum1 = 0.f;
#pragma unroll
            for (int nt = 0; nt < 8; nt++) {
                s[mt][nt][0] = __expf(s[mt][nt][0] - nm0); sum0 += s[mt][nt][0];
                s[mt][nt][1] = __expf(s[mt][nt][1] - nm0); sum0 += s[mt][nt][1];
                s[mt][nt][2] = __expf(s[mt][nt][2] - nm1); sum1 += s[mt][nt][2];
                s[mt][nt][3] = __expf(s[mt][nt][3] - nm1); sum1 += s[mt][nt][3];
            }
#pragma unroll
            for (int off = 1; off <= 2; off <<= 1) {
                sum0 += __shfl_xor_sync(0xFFFFFFFFu, sum0, off);
                sum1 += __shfl_xor_sync(0xFFFFFFFFu, sum1, off);
            }
            lrow[mt][0] = lrow[mt][0] * al0 + sum0;
            lrow[mt][1] = lrow[mt][1] * al1 + sum1;
            mrow[mt][0] = nm0;  mrow[mt][1] = nm1;
#pragma unroll
            for (int nt = 0; nt < 8; nt++) {
                of[mt][nt][0] *= al0; of[mt][nt][1] *= al0;
                of[mt][nt][2] *= al1; of[mt][nt][3] *= al1;
            }
        }

#pragma unroll
        for (int mt = 0; mt < 2; mt++) {
            int wr = wbase + mt * 16 + g;
#pragma unroll
            for (int nt = 0; nt < 8; nt++) {
                int pc = nt * 8 + 2 * tg;
                *(uint2*)&Ps[wr * PST + pc] =
                    make_uint2(f2tf(s[mt][nt][0]), f2tf(s[mt][nt][1]));
                *(uint2*)&Ps[(wr + 8) * PST + pc] =
                    make_uint2(f2tf(s[mt][nt][2]), f2tf(s[mt][nt][3]));
            }
        }
        __syncwarp();

        if (kt < ktmax) {
#pragma unroll
            for (int it = 0; it < 8; it++) {
                size_t gidx = hoff + (size_t)((kt + 1) * 64 + it * 8 + skey) * DM + sd4;
                pk[it] = *(const float4*)&k[gidx];
                pv[it] = *(const float4*)&v[gidx];
            }
        }

#pragma unroll
        for (int ks = 0; ks < 8; ks++) {
            int kc = ks * 8 + tg;
            uint32_t a[2][4];
#pragma unroll
            for (int mt = 0; mt < 2; mt++) {
                int wr = wbase + mt * 16 + g;
                a[mt][0] = Ps[wr * PST + kc];
                a[mt][1] = Ps[(wr + 8) * PST + kc];
                a[mt][2] = Ps[wr * PST + kc + 4];
                a[mt][3] = Ps[(wr + 8) * PST + kc + 4];
            }
#pragma unroll
            for (int nt = 0; nt < 8; nt++) {
                uint32_t b0 = Vs[kc * VST + nt * 8 + g];
                uint32_t b1 = Vs[(kc + 4) * VST + nt * 8 + g];
                mma_tf32(of[0][nt], a[0][0], a[0][1], a[0][2], a[0][3], b0, b1);
                mma_tf32(of[1][nt], a[1][0], a[1][1], a[1][2], a[1][3], b0, b1);
            }
        }
        __syncthreads();
    }

#pragma unroll
    for (int mt = 0; mt < 2; mt++) {
        float inv0 = 1.f / lrow[mt][0], inv1 = 1.f / lrow[mt][1];
        int r0 = qrow0 + mt * 16;
#pragma unroll
        for (int nt = 0; nt < 8; nt++) {
            size_t c = hoff + nt * 8 + 2 * tg;
            *(float2*)&o[(size_t)r0 * DM + c] =
                make_float2(of[mt][nt][0] * inv0, of[mt][nt][1] * inv0);
            *(float2*)&o[(size_t)(r0 + 8) * DM + c] =
                make_float2(of[mt][nt][2] * inv1, of[mt][nt][3] * inv1);
        }
    }
}

// ---------------------------------------------------------------------------
// Launch
// ---------------------------------------------------------------------------
extern "C" void kernel_launch(void* const* d_in, const int* in_sizes, int n_in,
                              void* d_out, int out_size)
{
    const float* Q  = (const float*)d_in[0];
    const float* K  = (const float*)d_in[1];
    const float* V  = (const float*)d_in[2];
    const float* Wq = (const float*)d_in[3];
    const float* Wk = (const float*)d_in[4];
    const float* Wv = (const float*)d_in[5];
    const float* Wo = (const float*)d_in[6];
    const float* bo = (const float*)d_in[7];
    float* out = (float*)d_out;

    float *gq, *gk, *gv, *ga;
    cudaGetSymbolAddress((void**)&gq, g_q);
    cudaGetSymbolAddress((void**)&gk, g_k);
    cudaGetSymbolAddress((void**)&gv, g_v);
    cudaGetSymbolAddress((void**)&ga, g_att);

    static bool attr_set = false;
    if (!attr_set) {
        cudaFuncSetAttribute(attn_mma,
                             cudaFuncAttributeMaxDynamicSharedMemorySize,
                             ATTN_SMEM);
        attr_set = true;
    }

    dim3 gproj(DM / 64, S_LEN / 256, 3);   // (12, 16, 3) fused QKV, 256m tiles
    proj3_mma<<<gproj, 128>>>(Q, K, V, Wq, Wk, Wv, gq, gk, gv);

    dim3 gattn(S_LEN / 128, NH);           // (32, 12)
    attn_mma<<<gattn, 128, ATTN_SMEM>>>(gq, gk, gv, ga);

    dim3 gout(DM / 64, S_LEN / 128);       // (12, 32)
    gemm_bias_mma<<<gout, 128>>>(ga, Wo, bo, out);
}

// round 10
// speedup vs baseline: 1.6024x; 1.6024x over previous
#include <cuda_runtime.h>
#include <stdint.h>

#define S_LEN 4096
#define DM    768
#define NH    12
#define HD    64

// Scratch (no cudaMalloc allowed)
__device__ float g_q[S_LEN * DM];
__device__ float g_k[S_LEN * DM];
__device__ float g_v[S_LEN * DM];
__device__ float g_att[S_LEN * DM];

// pack two f32 -> f16x2 word, lo in low half (PTX cvt: first src -> HIGH)
__device__ __forceinline__ uint32_t f2h2(float lo, float hi) {
    uint32_t r;
    asm("cvt.rn.f16x2.f32 %0, %1, %2;" : "=r"(r) : "f"(hi), "f"(lo));
    return r;
}

__device__ __forceinline__ void mma_f16(float c[4],
    uint32_t a0, uint32_t a1, uint32_t a2, uint32_t a3,
    uint32_t b0, uint32_t b1)
{
    asm volatile(
        "mma.sync.aligned.m16n8k16.row.col.f32.f16.f16.f32 "
        "{%0,%1,%2,%3}, {%4,%5,%6,%7}, {%8,%9}, {%0,%1,%2,%3};"
        : "+f"(c[0]), "+f"(c[1]), "+f"(c[2]), "+f"(c[3])
        : "r"(a0), "r"(a1), "r"(a2), "r"(a3), "r"(b0), "r"(b1));
}

// ---------------------------------------------------------------------------
// GEMM fp16: C[M,N] = A[M,K] @ B[K,N] (+bias). Block 128x64, Ktile 32,
// 128 thr = 4 warps x (32m x 64n). k16 mma -> 32 mma/tile, 48 LDS/tile.
// Ash[r][kw] (kw = k/2, f16x2), Bsp[kp][n] (word = {B[2kp][n], B[2kp+1][n]}).
// ---------------------------------------------------------------------------
#define AST2 20
#define BST2 72

__device__ __forceinline__ void gemm_body_f16(
    const float* __restrict__ A, const float* __restrict__ B,
    const float* __restrict__ bias, float* __restrict__ C,
    int N, int K, int bx, int by)
{
    __shared__ uint32_t Ash[128 * AST2];   // 10240 B
    __shared__ uint32_t Bsp[16 * BST2];    //  4608 B

    const int tid  = threadIdx.x;
    const int warp = tid >> 5, lane = tid & 31;
    const int g = lane >> 2, tg = lane & 3;
    const int m0 = by * 128, n0 = bx * 64;
    const int wbase = warp * 32;

    float acc[2][8][4];
#pragma unroll
    for (int mt = 0; mt < 2; mt++)
#pragma unroll
        for (int nt = 0; nt < 8; nt++)
#pragma unroll
            for (int c = 0; c < 4; c++) acc[mt][nt][c] = 0.f;

    // prefetch tile 0: A in 4 units (8 k each), B in 2 units (keypair x 4n)
    float4 ra[4][2], rb[2][2];
#pragma unroll
    for (int it = 0; it < 4; it++) {
        int idx = it * 128 + tid;
        int r = idx >> 2, u = idx & 3;
        ra[it][0] = *(const float4*)&A[(size_t)(m0 + r) * K + u * 8];
        ra[it][1] = *(const float4*)&A[(size_t)(m0 + r) * K + u * 8 + 4];
    }
#pragma unroll
    for (int it = 0; it < 2; it++) {
        int idx = it * 128 + tid;
        int kp = idx >> 4, n4 = (idx & 15) * 4;
        rb[it][0] = *(const float4*)&B[(size_t)(2 * kp) * N + n0 + n4];
        rb[it][1] = *(const float4*)&B[(size_t)(2 * kp + 1) * N + n0 + n4];
    }

    for (int k0 = 0; k0 < K; k0 += 32) {
        // stage current tile as fp16
#pragma unroll
        for (int it = 0; it < 4; it++) {
            int idx = it * 128 + tid;
            int r = idx >> 2, u = idx & 3;
            uint4 w;
            w.x = f2h2(ra[it][0].x, ra[it][0].y);
            w.y = f2h2(ra[it][0].z, ra[it][0].w);
            w.z = f2h2(ra[it][1].x, ra[it][1].y);
            w.w = f2h2(ra[it][1].z, ra[it][1].w);
            *(uint4*)&Ash[r * AST2 + u * 4] = w;
        }
#pragma unroll
        for (int it = 0; it < 2; it++) {
            int idx = it * 128 + tid;
            int kp = idx >> 4, n4 = (idx & 15) * 4;
            uint4 w;
            w.x = f2h2(rb[it][0].x, rb[it][1].x);
            w.y = f2h2(rb[it][0].y, rb[it][1].y);
            w.z = f2h2(rb[it][0].z, rb[it][1].z);
            w.w = f2h2(rb[it][0].w, rb[it][1].w);
            *(uint4*)&Bsp[kp * BST2 + n4] = w;
        }
        __syncthreads();

        // prefetch next tile
        if (k0 + 32 < K) {
#pragma unroll
            for (int it = 0; it < 4; it++) {
                int idx = it * 128 + tid;
                int r = idx >> 2, u = idx & 3;
                ra[it][0] = *(const float4*)&A[(size_t)(m0 + r) * K + k0 + 32 + u * 8];
                ra[it][1] = *(const float4*)&A[(size_t)(m0 + r) * K + k0 + 32 + u * 8 + 4];
            }
#pragma unroll
            for (int it = 0; it < 2; it++) {
                int idx = it * 128 + tid;
                int kp = idx >> 4, n4 = (idx & 15) * 4;
                rb[it][0] = *(const float4*)&B[(size_t)(k0 + 32 + 2 * kp) * N + n0 + n4];
                rb[it][1] = *(const float4*)&B[(size_t)(k0 + 32 + 2 * kp + 1) * N + n0 + n4];
            }
        }

#pragma unroll
        for (int c = 0; c < 2; c++) {
            int kcw = c * 8 + tg;
            uint32_t a[2][4];
#pragma unroll
            for (int mt = 0; mt < 2; mt++) {
                int r = wbase + mt * 16 + g;
                a[mt][0] = Ash[r * AST2 + kcw];
                a[mt][1] = Ash[(r + 8) * AST2 + kcw];
                a[mt][2] = Ash[r * AST2 + kcw + 4];
                a[mt][3] = Ash[(r + 8) * AST2 + kcw + 4];
            }
#pragma unroll
            for (int nt = 0; nt < 8; nt++) {
                int cn = nt * 8 + g;
                uint32_t b0 = Bsp[kcw * BST2 + cn];
                uint32_t b1 = Bsp[(kcw + 4) * BST2 + cn];
                mma_f16(acc[0][nt], a[0][0], a[0][1], a[0][2], a[0][3], b0, b1);
                mma_f16(acc[1][nt], a[1][0], a[1][1], a[1][2], a[1][3], b0, b1);
            }
        }
        __syncthreads();
    }

#pragma unroll
    for (int mt = 0; mt < 2; mt++) {
#pragma unroll
        for (int nt = 0; nt < 8; nt++) {
            int r = m0 + wbase + mt * 16 + g;
            int c = n0 + nt * 8 + 2 * tg;
            float b0 = 0.f, b1 = 0.f;
            if (bias) { b0 = bias[c]; b1 = bias[c + 1]; }
            *(float2*)&C[(size_t)r * N + c] =
                make_float2(acc[mt][nt][0] + b0, acc[mt][nt][1] + b1);
            *(float2*)&C[(size_t)(r + 8) * N + c] =
                make_float2(acc[mt][nt][2] + b0, acc[mt][nt][3] + b1);
        }
    }
}

__global__ __launch_bounds__(128) void proj3_mma(
    const float* __restrict__ Q, const float* __restrict__ K,
    const float* __restrict__ V,
    const float* __restrict__ Wq, const float* __restrict__ Wk,
    const float* __restrict__ Wv,
    float* __restrict__ gq, float* __restrict__ gk, float* __restrict__ gv)
{
    const float* A;
    const float* B;
    float* C;
    if (blockIdx.z == 0)      { A = Q; B = Wq; C = gq; }
    else if (blockIdx.z == 1) { A = K; B = Wk; C = gk; }
    else                      { A = V; B = Wv; C = gv; }
    gemm_body_f16(A, B, nullptr, C, DM, DM, blockIdx.x, blockIdx.y);
}

__global__ __launch_bounds__(128) void gemm_bias_mma(
    const float* __restrict__ A, const float* __restrict__ B,
    const float* __restrict__ bias, float* __restrict__ C)
{
    gemm_body_f16(A, B, bias, C, DM, DM, blockIdx.x, blockIdx.y);
}

// ---------------------------------------------------------------------------
// Flash attention fp16, causal. Block = 128 q-rows x 1 head, 128 thr
// (4 warps x 32 rows). k16 mma; P stays in registers (C-frag -> A-frag
// repack); V packed by key-pairs at staging. K/V register prefetch.
// ---------------------------------------------------------------------------
#define QST2 36
#define KST2 36
#define VST2 72
// static SMEM: (128*36 + 64*36 + 32*72)*4 = 36864 B

__global__ __launch_bounds__(128, 2) void attn_mma(
    const float* __restrict__ q, const float* __restrict__ k,
    const float* __restrict__ v, float* __restrict__ o)
{
    __shared__ uint32_t Qs[128 * QST2];   // [q][dw]   f16x2 d-pairs
    __shared__ uint32_t Ks[64 * KST2];    // [key][dw]
    __shared__ uint32_t Vsp[32 * VST2];   // [keypair][dv] = {V[2kp][dv],V[2kp+1][dv]}

    const int h = blockIdx.y;
    const int t = blockIdx.x;
    const int iq = (t & 1) ? (31 - (t >> 1)) : (t >> 1);  // heavy/light interleave
    const int tid = threadIdx.x, warp = tid >> 5, lane = tid & 31;
    const int g = lane >> 2, tg = lane & 3;
    const size_t hoff = (size_t)h * HD;
    const int wbase = warp * 32;
    const int qrow0 = iq * 128 + wbase + g;   // thread rows: +0,+8,+16,+24

    const int skey = tid >> 4;              // 0..7
    const int sd4  = (tid & 15) * 4;        // 0..60

    // Q tile (128 x 64) -> fp16 SMEM
#pragma unroll
    for (int it = 0; it < 16; it++) {
        int idx = it * 128 + tid;
        int r = idx >> 4, d4 = (idx & 15) * 4;
        float4 val = *(const float4*)&q[(size_t)(iq * 128 + r) * DM + hoff + d4];
        *(uint2*)&Qs[r * QST2 + d4 / 2] =
            make_uint2(f2h2(val.x, val.y), f2h2(val.z, val.w));
    }

    float of[2][8][4];
#pragma unroll
    for (int mt = 0; mt < 2; mt++)
#pragma unroll
        for (int nt = 0; nt < 8; nt++)
#pragma unroll
            for (int c = 0; c < 4; c++) of[mt][nt][c] = 0.f;
    float mrow[2][2], lrow[2][2];
#pragma unroll
    for (int mt = 0; mt < 2; mt++) {
        mrow[mt][0] = mrow[mt][1] = -1e30f;
        lrow[mt][0] = lrow[mt][1] = 0.f;
    }

    // prologue prefetch tile 0
    float4 pk[8], pva[4], pvb[4];
#pragma unroll
    for (int it = 0; it < 8; it++)
        pk[it] = *(const float4*)&k[hoff + (size_t)(it * 8 + skey) * DM + sd4];
#pragma unroll
    for (int it = 0; it < 4; it++) {
        int kp = it * 8 + skey;
        pva[it] = *(const float4*)&v[hoff + (size_t)(2 * kp) * DM + sd4];
        pvb[it] = *(const float4*)&v[hoff + (size_t)(2 * kp + 1) * DM + sd4];
    }

    __syncthreads();

    const int ktmax = 2 * iq + 1;
    for (int kt = 0; kt <= ktmax; kt++) {
        // stage prefetched K/V as fp16
#pragma unroll
        for (int it = 0; it < 8; it++) {
            int key = it * 8 + skey;
            *(uint2*)&Ks[key * KST2 + sd4 / 2] =
                make_uint2(f2h2(pk[it].x, pk[it].y), f2h2(pk[it].z, pk[it].w));
        }
#pragma unroll
        for (int it = 0; it < 4; it++) {
            int kp = it * 8 + skey;
            uint4 w;
            w.x = f2h2(pva[it].x, pvb[it].x);
            w.y = f2h2(pva[it].y, pvb[it].y);
            w.z = f2h2(pva[it].z, pvb[it].z);
            w.w = f2h2(pva[it].w, pvb[it].w);
            *(uint4*)&Vsp[kp * VST2 + sd4] = w;
        }
        __syncthreads();

        // S = Q @ K^T  (4 k-chunks of 16 d)
        float s[2][8][4];
#pragma unroll
        for (int mt = 0; mt < 2; mt++)
#pragma unroll
            for (int nt = 0; nt < 8; nt++)
#pragma unroll
                for (int c = 0; c < 4; c++) s[mt][nt][c] = 0.f;

#pragma unroll
        for (int c = 0; c < 4; c++) {
            int kcw = c * 8 + tg;
            uint32_t a[2][4];
#pragma unroll
            for (int mt = 0; mt < 2; mt++) {
                int wr = wbase + mt * 16 + g;
                a[mt][0] = Qs[wr * QST2 + kcw];
                a[mt][1] = Qs[(wr + 8) * QST2 + kcw];
                a[mt][2] = Qs[wr * QST2 + kcw + 4];
                a[mt][3] = Qs[(wr + 8) * QST2 + kcw + 4];
            }
#pragma unroll
            for (int nt = 0; nt < 8; nt++) {
                int krow = nt * 8 + g;
                uint32_t b0 = Ks[krow * KST2 + kcw];
                uint32_t b1 = Ks[krow * KST2 + kcw + 4];
                mma_f16(s[0][nt], a[0][0], a[0][1], a[0][2], a[0][3], b0, b1);
                mma_f16(s[1][nt], a[1][0], a[1][1], a[1][2], a[1][3], b0, b1);
            }
        }

        // scale + causal mask (C-frag cols 2tg, 2tg+1)
        const bool need_mask = (kt >= 2 * iq);
#pragma unroll
        for (int mt = 0; mt < 2; mt++) {
            int r0 = qrow0 + mt * 16;
#pragma unroll
            for (int nt = 0; nt < 8; nt++) {
                s[mt][nt][0] *= 0.125f; s[mt][nt][1] *= 0.125f;
                s[mt][nt][2] *= 0.125f; s[mt][nt][3] *= 0.125f;
                if (need_mask) {
                    int col = kt * 64 + nt * 8 + 2 * tg;
                    if (col     > r0)     s[mt][nt][0] = -1e30f;
                    if (col + 1 > r0)     s[mt][nt][1] = -1e30f;
                    if (col     > r0 + 8) s[mt][nt][2] = -1e30f;
                    if (col + 1 > r0 + 8) s[mt][nt][3] = -1e30f;
                }
            }
        }

        // online softmax (rows spread over 4 tg-lanes)
#pragma unroll
        for (int mt = 0; mt < 2; mt++) {
            float rm0 = -1e30f, rm1 = -1e30f;
#pragma unroll
            for (int nt = 0; nt < 8; nt++) {
                rm0 = fmaxf(rm0, fmaxf(s[mt][nt][0], s[mt][nt][1]));
                rm1 = fmaxf(rm1, fmaxf(s[mt][nt][2], s[mt][nt][3]));
            }
#pragma unroll
            for (int off = 1; off <= 2; off <<= 1) {
                rm0 = fmaxf(rm0, __shfl_xor_sync(0xFFFFFFFFu, rm0, off));
                rm1 = fmaxf(rm1, __shfl_xor_sync(0xFFFFFFFFu, rm1, off));
            }
            float nm0 = fmaxf(mrow[mt][0], rm0), nm1 = fmaxf(mrow[mt][1], rm1);
            float al0 = __expf(mrow[mt][0] - nm0), al1 = __expf(mrow[mt][1] - nm1);
            float sum0 = 0.f, sum1 = 0.f;
#pragma unroll
            for (int nt = 0; nt < 8; nt++) {
                s[mt][nt][0] = __expf(s[mt][nt][0] - nm0); sum0 += s[mt][nt][0];
                s[mt][nt][1] = __expf(s[mt][nt][1] - nm0); sum0 += s[mt][nt][1];
                s[mt][nt][2] = __expf(s[mt][nt][2] - nm1); sum1 += s[mt][nt][2];
                s[mt][nt][3] = __expf(s[mt][nt][3] - nm1); sum1 += s[mt][nt][3];
            }
#pragma unroll
            for (int off = 1; off <= 2; off <<= 1) {
                sum0 += __shfl_xor_sync(0xFFFFFFFFu, sum0, off);
                sum1 += __shfl_xor_sync(0xFFFFFFFFu, sum1, off);
            }
            lrow[mt][0] = lrow[mt][0] * al0 + sum0;
            lrow[mt][1] = lrow[mt][1] * al1 + sum1;
            mrow[mt][0] = nm0;  mrow[mt][1] = nm1;
#pragma unroll
            for (int nt = 0; nt < 8; nt++) {
                of[mt][nt][0] *= al0; of[mt][nt][1] *= al0;
                of[mt][nt][2] *= al1; of[mt][nt][3] *= al1;
            }
        }

        // pack P: S C-frags -> PV A-frags entirely in registers.
        uint32_t ah[2][4][4];
#pragma unroll
        for (int mt = 0; mt < 2; mt++)
#pragma unroll
            for (int c = 0; c < 4; c++) {
                ah[mt][c][0] = f2h2(s[mt][2 * c][0],     s[mt][2 * c][1]);
                ah[mt][c][1] = f2h2(s[mt][2 * c][2],     s[mt][2 * c][3]);
                ah[mt][c][2] = f2h2(s[mt][2 * c + 1][0], s[mt][2 * c + 1][1]);
                ah[mt][c][3] = f2h2(s[mt][2 * c + 1][2], s[mt][2 * c + 1][3]);
            }

        // prefetch next K/V tile (s dead; hides behind PV + next S)
        if (kt < ktmax) {
#pragma unroll
            for (int it = 0; it < 8; it++)
                pk[it] = *(const float4*)&k[hoff +
                    (size_t)((kt + 1) * 64 + it * 8 + skey) * DM + sd4];
#pragma unroll
            for (int it = 0; it < 4; it++) {
                int kp = it * 8 + skey;
                pva[it] = *(const float4*)&v[hoff +
                    (size_t)((kt + 1) * 64 + 2 * kp) * DM + sd4];
                pvb[it] = *(const float4*)&v[hoff +
                    (size_t)((kt + 1) * 64 + 2 * kp + 1) * DM + sd4];
            }
        }

        // O += P @ V
#pragma unroll
        for (int c = 0; c < 4; c++) {
            int kcw = c * 8 + tg;
#pragma unroll
            for (int nt = 0; nt < 8; nt++) {
                int cn = nt * 8 + g;
                uint32_t b0 = Vsp[kcw * VST2 + cn];
                uint32_t b1 = Vsp[(kcw + 4) * VST2 + cn];
                mma_f16(of[0][nt], ah[0][c][0], ah[0][c][1], ah[0][c][2], ah[0][c][3], b0, b1);
                mma_f16(of[1][nt], ah[1][c][0], ah[1][c][1], ah[1][c][2], ah[1][c][3], b0, b1);
            }
        }
        __syncthreads();   // protect Ks/Vsp before next tile store
    }

    // epilogue
#pragma unroll
    for (int mt = 0; mt < 2; mt++) {
        float inv0 = 1.f / lrow[mt][0], inv1 = 1.f / lrow[mt][1];
        int r0 = qrow0 + mt * 16;
#pragma unroll
        for (int nt = 0; nt < 8; nt++) {
            size_t c = hoff + nt * 8 + 2 * tg;
            *(float2*)&o[(size_t)r0 * DM + c] =
                make_float2(of[mt][nt][0] * inv0, of[mt][nt][1] * inv0);
            *(float2*)&o[(size_t)(r0 + 8) * DM + c] =
                make_float2(of[mt][nt][2] * inv1, of[mt][nt][3] * inv1);
        }
    }
}

// ---------------------------------------------------------------------------
// Launch
// ---------------------------------------------------------------------------
extern "C" void kernel_launch(void* const* d_in, const int* in_sizes, int n_in,
                              void* d_out, int out_size)
{
    const float* Q  = (const float*)d_in[0];
    const float* K  = (const float*)d_in[1];
    const float* V  = (const float*)d_in[2];
    const float* Wq = (const float*)d_in[3];
    const float* Wk = (const float*)d_in[4];
    const float* Wv = (const float*)d_in[5];
    const float* Wo = (const float*)d_in[6];
    const float* bo = (const float*)d_in[7];
    float* out = (float*)d_out;

    float *gq, *gk, *gv, *ga;
    cudaGetSymbolAddress((void**)&gq, g_q);
    cudaGetSymbolAddress((void**)&gk, g_k);
    cudaGetSymbolAddress((void**)&gv, g_v);
    cudaGetSymbolAddress((void**)&ga, g_att);

    dim3 gproj(DM / 64, S_LEN / 128, 3);   // (12, 32, 3) fused QKV
    proj3_mma<<<gproj, 128>>>(Q, K, V, Wq, Wk, Wv, gq, gk, gv);

    dim3 gattn(S_LEN / 128, NH);           // (32, 12)
    attn_mma<<<gattn, 128>>>(gq, gk, gv, ga);

    dim3 gout(DM / 64, S_LEN / 128);       // (12, 32)
    gemm_bias_mma<<<gout, 128>>>(ga, Wo, bo, out);
}

// round 11
// speedup vs baseline: 1.8195x; 1.1355x over previous
#include <cuda_runtime.h>
#include <cuda_fp16.h>
#include <stdint.h>

#define S_LEN 4096
#define DM    768
#define NH    12
#define HD    64
#define KW    (DM / 2)   // 384 key-pair rows in packed weights

// ---------------------------------------------------------------------------
// Scratch (no cudaMalloc allowed). All fp16/packed, 16B-aligned for cp.async.
// ---------------------------------------------------------------------------
__device__ __align__(16) __half   hQ[S_LEN * DM], hK[S_LEN * DM], hV[S_LEN * DM];
__device__ __align__(16) uint32_t pWq[KW * DM], pWk[KW * DM], pWv[KW * DM], pWo[KW * DM];
__device__ __align__(16) __half   g_q16[S_LEN * DM];
__device__ __align__(16) __half   g_k16[S_LEN * DM];
__device__ __align__(16) __half   g_vT [DM * S_LEN];   // [h*64+dv][key]
__device__ __align__(16) __half   g_a16[S_LEN * DM];

// pack two f32 -> f16x2 word, lo in low half (cvt packs first src HIGH)
__device__ __forceinline__ uint32_t f2h2(float lo, float hi) {
    uint32_t r;
    asm("cvt.rn.f16x2.f32 %0, %1, %2;" : "=r"(r) : "f"(hi), "f"(lo));
    return r;
}

__device__ __forceinline__ void mma_f16(float c[4],
    uint32_t a0, uint32_t a1, uint32_t a2, uint32_t a3,
    uint32_t b0, uint32_t b1)
{
    asm volatile(
        "mma.sync.aligned.m16n8k16.row.col.f32.f16.f16.f32 "
        "{%0,%1,%2,%3}, {%4,%5,%6,%7}, {%8,%9}, {%0,%1,%2,%3};"
        : "+f"(c[0]), "+f"(c[1]), "+f"(c[2]), "+f"(c[3])
        : "r"(a0), "r"(a1), "r"(a2), "r"(a3), "r"(b0), "r"(b1));
}

__device__ __forceinline__ void cp16(uint32_t dst_smem, const void* src) {
    asm volatile("cp.async.cg.shared.global [%0], [%1], 16;"
                 :: "r"(dst_smem), "l"(src));
}
#define CP_COMMIT()   asm volatile("cp.async.commit_group;" ::: "memory")
#define CP_WAIT_ALL() asm volatile("cp.async.wait_all;" ::: "memory")

// ---------------------------------------------------------------------------
// Prologue 1: convert fp32 inputs Q,K,V -> fp16 (8 elems/thread, exact grid)
// ---------------------------------------------------------------------------
__global__ __launch_bounds__(256) void cvt3(
    const float* __restrict__ Q, const float* __restrict__ K,
    const float* __restrict__ V)
{
    const float* src = (blockIdx.y == 0) ? Q : (blockIdx.y == 1) ? K : V;
    __half* dst = (blockIdx.y == 0) ? hQ : (blockIdx.y == 1) ? hK : hV;
    int i = blockIdx.x * 256 + threadIdx.x;           // 16B chunk index
    float4 a = ((const float4*)src)[2 * i];
    float4 b = ((const float4*)src)[2 * i + 1];
    uint4 w = make_uint4(f2h2(a.x, a.y), f2h2(a.z, a.w),
                         f2h2(b.x, b.y), f2h2(b.z, b.w));
    ((uint4*)dst)[i] = w;
}

// ---------------------------------------------------------------------------
// Prologue 2: pack weights: P[kp*DM + n] = {W[2kp][n], W[2kp+1][n]} fp16x2
// ---------------------------------------------------------------------------
__global__ __launch_bounds__(256) void packw(
    const float* __restrict__ Wq, const float* __restrict__ Wk,
    const float* __restrict__ Wv, const float* __restrict__ Wo)
{
    const float* W = (blockIdx.y == 0) ? Wq : (blockIdx.y == 1) ? Wk :
                     (blockIdx.y == 2) ? Wv : Wo;
    uint32_t* P = (blockIdx.y == 0) ? pWq : (blockIdx.y == 1) ? pWk :
                  (blockIdx.y == 2) ? pWv : pWo;
    int i = blockIdx.x * 256 + threadIdx.x;           // word index
    int kp = i / DM, n = i - kp * DM;
    P[i] = f2h2(W[(size_t)(2 * kp) * DM + n], W[(size_t)(2 * kp + 1) * DM + n]);
}

// ---------------------------------------------------------------------------
// GEMM fp16, mt=4: block tile 256x64, Ktile 32, 128 thr = 4 warps x (64m,64n).
// cp.async double-buffered; A raw fp16 rows (stride 20 words, conflict-free),
// B packed key-pair words (stride 72, conflict-free).
// mode: 0 = fp16 out, 1 = fp16 transposed out (g_vT), 2 = f32 + bias out.
// ---------------------------------------------------------------------------
#define GA_ST 20
#define GB_ST 72
#define GBUF  (256 * GA_ST + 16 * GB_ST)        // 6272 words per buffer
#define GEMM_SMEM (2 * GBUF * 4)                // 50176 B

__device__ __forceinline__ void gemm16_body(
    const __half* __restrict__ A, const uint32_t* __restrict__ Bp,
    const float* __restrict__ bias, void* __restrict__ Cout,
    int bx, int by, int mode)
{
    extern __shared__ uint32_t sm[];
    const uint32_t sb = (uint32_t)__cvta_generic_to_shared(sm);

    const int tid  = threadIdx.x;
    const int warp = tid >> 5, lane = tid & 31;
    const int g = lane >> 2, tg = lane & 3;
    const int m0 = by * 256, n0 = bx * 64;
    const int wbase = warp * 64;

    float acc[4][8][4];
#pragma unroll
    for (int mt = 0; mt < 4; mt++)
#pragma unroll
        for (int nt = 0; nt < 8; nt++)
#pragma unroll
            for (int c = 0; c < 4; c++) acc[mt][nt][c] = 0.f;

    // async-copy one k-tile into buffer b
    auto issue = [&](int t, int b) {
        uint32_t base = sb + (uint32_t)(b * GBUF) * 4;
#pragma unroll
        for (int it = 0; it < 8; it++) {
            int idx = it * 128 + tid;
            int r = idx >> 2, c16 = idx & 3;
            cp16(base + (uint32_t)(r * GA_ST + c16 * 4) * 4,
                 &A[(size_t)(m0 + r) * DM + t * 32 + c16 * 8]);
        }
#pragma unroll
        for (int it = 0; it < 2; it++) {
            int idx = it * 128 + tid;
            int kp = idx >> 4, nc = idx & 15;
            cp16(base + (uint32_t)(256 * GA_ST + kp * GB_ST + nc * 4) * 4,
                 &Bp[(size_t)(t * 16 + kp) * DM + n0 + nc * 4]);
        }
        CP_COMMIT();
    };

    issue(0, 0);

    const int NT = DM / 32;   // 24
    for (int t = 0; t < NT; t++) {
        CP_WAIT_ALL();
        __syncthreads();
        if (t + 1 < NT) issue(t + 1, (t + 1) & 1);

        const uint32_t* Ab = sm + (t & 1) * GBUF;
        const uint32_t* Bb = Ab + 256 * GA_ST;

#pragma unroll
        for (int c = 0; c < 2; c++) {
            int kcw = c * 8 + tg;
            uint32_t a[4][4];
#pragma unroll
            for (int mt = 0; mt < 4; mt++) {
                int r = wbase + mt * 16 + g;
                a[mt][0] = Ab[r * GA_ST + kcw];
                a[mt][1] = Ab[(r + 8) * GA_ST + kcw];
                a[mt][2] = Ab[r * GA_ST + kcw + 4];
                a[mt][3] = Ab[(r + 8) * GA_ST + kcw + 4];
            }
#pragma unroll
            for (int nt = 0; nt < 8; nt++) {
                int cn = nt * 8 + g;
                uint32_t b0 = Bb[kcw * GB_ST + cn];
                uint32_t b1 = Bb[(kcw + 4) * GB_ST + cn];
#pragma unroll
                for (int mt = 0; mt < 4; mt++)
                    mma_f16(acc[mt][nt], a[mt][0], a[mt][1], a[mt][2], a[mt][3],
                            b0, b1);
            }
        }
        __syncthreads();
    }

    // epilogue
    if (mode == 0) {
        uint32_t* out = (uint32_t*)Cout;
#pragma unroll
        for (int mt = 0; mt < 4; mt++)
#pragma unroll
            for (int nt = 0; nt < 8; nt++) {
                int r = m0 + wbase + mt * 16 + g;
                int c = n0 + nt * 8 + 2 * tg;
                out[((size_t)r * DM + c) >> 1] =
                    f2h2(acc[mt][nt][0], acc[mt][nt][1]);
                out[((size_t)(r + 8) * DM + c) >> 1] =
                    f2h2(acc[mt][nt][2], acc[mt][nt][3]);
            }
    } else if (mode == 1) {
        __half* out = (__half*)Cout;
#pragma unroll
        for (int mt = 0; mt < 4; mt++)
#pragma unroll
            for (int nt = 0; nt < 8; nt++) {
                int r = m0 + wbase + mt * 16 + g;
                int c = n0 + nt * 8 + 2 * tg;
                out[(size_t)c * S_LEN + r]           = __float2half_rn(acc[mt][nt][0]);
                out[(size_t)(c + 1) * S_LEN + r]     = __float2half_rn(acc[mt][nt][1]);
                out[(size_t)c * S_LEN + r + 8]       = __float2half_rn(acc[mt][nt][2]);
                out[(size_t)(c + 1) * S_LEN + r + 8] = __float2half_rn(acc[mt][nt][3]);
            }
    } else {
        float* out = (float*)Cout;
#pragma unroll
        for (int mt = 0; mt < 4; mt++)
#pragma unroll
            for (int nt = 0; nt < 8; nt++) {
                int r = m0 + wbase + mt * 16 + g;
                int c = n0 + nt * 8 + 2 * tg;
                float b0 = bias[c], b1 = bias[c + 1];
                *(float2*)&out[(size_t)r * DM + c] =
                    make_float2(acc[mt][nt][0] + b0, acc[mt][nt][1] + b1);
                *(float2*)&out[(size_t)(r + 8) * DM + c] =
                    make_float2(acc[mt][nt][2] + b0, acc[mt][nt][3] + b1);
            }
    }
}

__global__ __launch_bounds__(128) void proj3(float* dummy) {
    if (blockIdx.z == 0)
        gemm16_body(hQ, pWq, nullptr, g_q16, blockIdx.x, blockIdx.y, 0);
    else if (blockIdx.z == 1)
        gemm16_body(hK, pWk, nullptr, g_k16, blockIdx.x, blockIdx.y, 0);
    else
        gemm16_body(hV, pWv, nullptr, g_vT, blockIdx.x, blockIdx.y, 1);
}

__global__ __launch_bounds__(128) void outg(const float* bias, float* out) {
    gemm16_body(g_a16, pWo, bias, out, blockIdx.x, blockIdx.y, 2);
}

// ---------------------------------------------------------------------------
// Flash attention fp16: 128 q-rows x 1 head, 128 thr (4 warps x 32 rows).
// Q-fragments resident in registers; K/V via cp.async double-buffer;
// P in registers (C-frag -> A-frag repack). V from g_vT (native b-frag).
// ---------------------------------------------------------------------------
#define KT_ST 36
#define ABUF  (2 * 64 * KT_ST)      // K + V per buffer = 4608 words

__global__ __launch_bounds__(128, 2) void attn16(float* dummy)
{
    __shared__ uint32_t sm[2 * ABUF];   // 36864 B
    const uint32_t sb = (uint32_t)__cvta_generic_to_shared(sm);

    const int h = blockIdx.y;
    const int t = blockIdx.x;
    const int iq = (t & 1) ? (31 - (t >> 1)) : (t >> 1);  // heavy/light interleave
    const int tid = threadIdx.x, warp = tid >> 5, lane = tid & 31;
    const int g = lane >> 2, tg = lane & 3;
    const int hoff = h * HD;
    const int wbase = warp * 32;
    const int qrow0 = iq * 128 + wbase + g;   // rows +0,+8,+16,+24

    // Q fragments straight from gmem fp16 (once per block)
    const uint32_t* qw = (const uint32_t*)g_q16;
    uint32_t qf[2][4][4];
#pragma unroll
    for (int mt = 0; mt < 2; mt++) {
        size_t b0 = ((size_t)(qrow0 + mt * 16) * DM + hoff) >> 1;
        size_t b1 = ((size_t)(qrow0 + mt * 16 + 8) * DM + hoff) >> 1;
#pragma unroll
        for (int c = 0; c < 4; c++) {
            qf[mt][c][0] = qw[b0 + c * 8 + tg];
            qf[mt][c][1] = qw[b1 + c * 8 + tg];
            qf[mt][c][2] = qw[b0 + c * 8 + tg + 4];
            qf[mt][c][3] = qw[b1 + c * 8 + tg + 4];
        }
    }

    float of[2][8][4];
#pragma unroll
    for (int mt = 0; mt < 2; mt++)
#pragma unroll
        for (int nt = 0; nt < 8; nt++)
#pragma unroll
            for (int c = 0; c < 4; c++) of[mt][nt][c] = 0.f;
    float mrow[2][2], lrow[2][2];
#pragma unroll
    for (int mt = 0; mt < 2; mt++) {
        mrow[mt][0] = mrow[mt][1] = -1e30f;
        lrow[mt][0] = lrow[mt][1] = 0.f;
    }

    // issue one K/V tile into buffer b
    auto issue = [&](int kt, int b) {
        uint32_t base = sb + (uint32_t)(b * ABUF) * 4;
#pragma unroll
        for (int it = 0; it < 4; it++) {
            int idx = it * 128 + tid;
            int r = idx >> 3, c16 = idx & 7;
            cp16(base + (uint32_t)(r * KT_ST + c16 * 4) * 4,
                 &g_k16[(size_t)(kt * 64 + r) * DM + hoff + c16 * 8]);
            cp16(base + (uint32_t)(64 * KT_ST + r * KT_ST + c16 * 4) * 4,
                 &g_vT[(size_t)(hoff + r) * S_LEN + kt * 64 + c16 * 8]);
        }
        CP_COMMIT();
    };

    issue(0, 0);

    const int ktmax = 2 * iq + 1;
    for (int kt = 0; kt <= ktmax; kt++) {
        CP_WAIT_ALL();
        __syncthreads();
        if (kt < ktmax) issue(kt + 1, (kt + 1) & 1);

        const uint32_t* Kb = sm + (kt & 1) * ABUF;
        const uint32_t* Vb = Kb + 64 * KT_ST;

        // S = Q @ K^T
        float s[2][8][4];
#pragma unroll
        for (int mt = 0; mt < 2; mt++)
#pragma unroll
            for (int nt = 0; nt < 8; nt++)
#pragma unroll
                for (int c = 0; c < 4; c++) s[mt][nt][c] = 0.f;

#pragma unroll
        for (int c = 0; c < 4; c++) {
            int kcw = c * 8 + tg;
#pragma unroll
            for (int nt = 0; nt < 8; nt++) {
                int krow = nt * 8 + g;
                uint32_t b0 = Kb[krow * KT_ST + kcw];
                uint32_t b1 = Kb[krow * KT_ST + kcw + 4];
                mma_f16(s[0][nt], qf[0][c][0], qf[0][c][1], qf[0][c][2], qf[0][c][3], b0, b1);
                mma_f16(s[1][nt], qf[1][c][0], qf[1][c][1], qf[1][c][2], qf[1][c][3], b0, b1);
            }
        }

        // scale + causal mask
        const bool need_mask = (kt >= 2 * iq);
#pragma unroll
        for (int mt = 0; mt < 2; mt++) {
            int r0 = qrow0 + mt * 16;
#pragma unroll
            for (int nt = 0; nt < 8; nt++) {
                s[mt][nt][0] *= 0.125f; s[mt][nt][1] *= 0.125f;
                s[mt][nt][2] *= 0.125f; s[mt][nt][3] *= 0.125f;
                if (need_mask) {
                    int col = kt * 64 + nt * 8 + 2 * tg;
                    if (col     > r0)     s[mt][nt][0] = -1e30f;
                    if (col + 1 > r0)     s[mt][nt][1] = -1e30f;
                    if (col     > r0 + 8) s[mt][nt][2] = -1e30f;
                    if (col + 1 > r0 + 8) s[mt][nt][3] = -1e30f;
                }
            }
        }

        // online softmax
#pragma unroll
        for (int mt = 0; mt < 2; mt++) {
            float rm0 = -1e30f, rm1 = -1e30f;
#pragma unroll
            for (int nt = 0; nt < 8; nt++) {
                rm0 = fmaxf(rm0, fmaxf(s[mt][nt][0], s[mt][nt][1]));
                rm1 = fmaxf(rm1, fmaxf(s[mt][nt][2], s[mt][nt][3]));
            }
#pragma unroll
            for (int off = 1; off <= 2; off <<= 1) {
                rm0 = fmaxf(rm0, __shfl_xor_sync(0xFFFFFFFFu, rm0, off));
                rm1 = fmaxf(rm1, __shfl_xor_sync(0xFFFFFFFFu, rm1, off));
            }
            float nm0 = fmaxf(mrow[mt][0], rm0), nm1 = fmaxf(mrow[mt][1], rm1);
            float al0 = __expf(mrow[mt][0] - nm0), al1 = __expf(mrow[mt][1] - nm1);
            float sum0 = 0.f, sum1 = 0.f;
#pragma unroll
            for (int nt = 0; nt < 8; nt++) {
                s[mt][nt][0] = __expf(s[mt][nt][0] - nm0); sum0 += s[mt][nt][0];
                s[mt][nt][1] = __expf(s[mt][nt][1] - nm0); sum0 += s[mt][nt][1];
                s[mt][nt][2] = __expf(s[mt][nt][2] - nm1); sum1 += s[mt][nt][2];
                s[mt][nt][3] = __expf(s[mt][nt][3] - nm1); sum1 += s[mt][nt][3];
            }
#pragma unroll
            for (int off = 1; off <= 2; off <<= 1) {
                sum0 += __shfl_xor_sync(0xFFFFFFFFu, sum0, off);
                sum1 += __shfl_xor_sync(0xFFFFFFFFu, sum1, off);
            }
            lrow[mt][0] = lrow[mt][0] * al0 + sum0;
            lrow[mt][1] = lrow[mt][1] * al1 + sum1;
            mrow[mt][0] = nm0;  mrow[mt][1] = nm1;
#pragma unroll
            for (int nt = 0; nt < 8; nt++) {
                of[mt][nt][0] *= al0; of[mt][nt][1] *= al0;
                of[mt][nt][2] *= al1; of[mt][nt][3] *= al1;
            }
        }

        // pack P in registers
        uint32_t ah[2][4][4];
#pragma unroll
        for (int mt = 0; mt < 2; mt++)
#pragma unroll
            for (int c = 0; c < 4; c++) {
                ah[mt][c][0] = f2h2(s[mt][2 * c][0],     s[mt][2 * c][1]);
                ah[mt][c][1] = f2h2(s[mt][2 * c][2],     s[mt][2 * c][3]);
                ah[mt][c][2] = f2h2(s[mt][2 * c + 1][0], s[mt][2 * c + 1][1]);
                ah[mt][c][3] = f2h2(s[mt][2 * c + 1][2], s[mt][2 * c + 1][3]);
            }

        // O += P @ V  (b-frags native from transposed V)
#pragma unroll
        for (int c = 0; c < 4; c++) {
            int kcw = c * 8 + tg;
#pragma unroll
            for (int nt = 0; nt < 8; nt++) {
                int dvr = nt * 8 + g;
                uint32_t b0 = Vb[dvr * KT_ST + kcw];
                uint32_t b1 = Vb[dvr * KT_ST + kcw + 4];
                mma_f16(of[0][nt], ah[0][c][0], ah[0][c][1], ah[0][c][2], ah[0][c][3], b0, b1);
                mma_f16(of[1][nt], ah[1][c][0], ah[1][c][1], ah[1][c][2], ah[1][c][3], b0, b1);
            }
        }
    }

    // epilogue -> fp16 att buffer
    uint32_t* out = (uint32_t*)g_a16;
#pragma unroll
    for (int mt = 0; mt < 2; mt++) {
        float inv0 = 1.f / lrow[mt][0], inv1 = 1.f / lrow[mt][1];
        int r0 = qrow0 + mt * 16;
#pragma unroll
        for (int nt = 0; nt < 8; nt++) {
            int c = hoff + nt * 8 + 2 * tg;
            out[((size_t)r0 * DM + c) >> 1] =
                f2h2(of[mt][nt][0] * inv0, of[mt][nt][1] * inv0);
            out[((size_t)(r0 + 8) * DM + c) >> 1] =
                f2h2(of[mt][nt][2] * inv1, of[mt][nt][3] * inv1);
        }
    }
}

// ---------------------------------------------------------------------------
// Launch
// ---------------------------------------------------------------------------
extern "C" void kernel_launch(void* const* d_in, const int* in_sizes, int n_in,
                              void* d_out, int out_size)
{
    const float* Q  = (const float*)d_in[0];
    const float* K  = (const float*)d_in[1];
    const float* V  = (const float*)d_in[2];
    const float* Wq = (const float*)d_in[3];
    const float* Wk = (const float*)d_in[4];
    const float* Wv = (const float*)d_in[5];
    const float* Wo = (const float*)d_in[6];
    const float* bo = (const float*)d_in[7];
    float* out = (float*)d_out;

    static bool attr_set = false;
    if (!attr_set) {
        cudaFuncSetAttribute(proj3, cudaFuncAttributeMaxDynamicSharedMemorySize,
                             GEMM_SMEM);
        cudaFuncSetAttribute(outg, cudaFuncAttributeMaxDynamicSharedMemorySize,
                             GEMM_SMEM);
        attr_set = true;
    }

    cvt3<<<dim3(S_LEN * DM / 8 / 256, 3), 256>>>(Q, K, V);        // (1536, 3)
    packw<<<dim3(KW * DM / 256, 4), 256>>>(Wq, Wk, Wv, Wo);       // (1152, 4)

    proj3<<<dim3(DM / 64, S_LEN / 256, 3), 128, GEMM_SMEM>>>(nullptr);

    attn16<<<dim3(S_LEN / 128, NH), 128>>>(nullptr);

    outg<<<dim3(DM / 64, S_LEN / 256), 128, GEMM_SMEM>>>(bo, out);
}

// round 12
// speedup vs baseline: 1.9199x; 1.0552x over previous
#include <cuda_runtime.h>
#include <cuda_fp16.h>
#include <stdint.h>

#define S_LEN 4096
#define DM    768
#define NH    12
#define HD    64
#define KW    (DM / 2)   // 384 key-pair rows in packed weights

// Q prescale: 0.125 (1/sqrt(64)) * log2(e) -> scores in log2 domain
#define QSCALE 0.18033688011112042f
#define ONESH2 0x3C003C00u   // fp16x2 {1.0, 1.0}

// ---------------------------------------------------------------------------
// Scratch (no cudaMalloc allowed). All fp16/packed, 16B-aligned for cp.async.
// ---------------------------------------------------------------------------
__device__ __align__(16) __half   hQ[S_LEN * DM], hK[S_LEN * DM], hV[S_LEN * DM];
__device__ __align__(16) uint32_t pWq[KW * DM], pWk[KW * DM], pWv[KW * DM], pWo[KW * DM];
__device__ __align__(16) __half   g_q16[S_LEN * DM];
__device__ __align__(16) __half   g_k16[S_LEN * DM];
__device__ __align__(16) __half   g_vT [DM * S_LEN];   // [h*64+dv][key]
__device__ __align__(16) __half   g_a16[S_LEN * DM];

// pack two f32 -> f16x2 word, lo in low half (cvt packs first src HIGH)
__device__ __forceinline__ uint32_t f2h2(float lo, float hi) {
    uint32_t r;
    asm("cvt.rn.f16x2.f32 %0, %1, %2;" : "=r"(r) : "f"(hi), "f"(lo));
    return r;
}

__device__ __forceinline__ uint32_t hsub2u(uint32_t a, uint32_t b) {
    uint32_t r;
    asm("sub.rn.f16x2 %0, %1, %2;" : "=r"(r) : "r"(a), "r"(b));
    return r;
}

__device__ __forceinline__ uint32_t ex2h2(uint32_t x) {
    uint32_t r;
    asm("ex2.approx.f16x2 %0, %1;" : "=r"(r) : "r"(x));
    return r;
}

__device__ __forceinline__ void mma_f16(float c[4],
    uint32_t a0, uint32_t a1, uint32_t a2, uint32_t a3,
    uint32_t b0, uint32_t b1)
{
    asm volatile(
        "mma.sync.aligned.m16n8k16.row.col.f32.f16.f16.f32 "
        "{%0,%1,%2,%3}, {%4,%5,%6,%7}, {%8,%9}, {%0,%1,%2,%3};"
        : "+f"(c[0]), "+f"(c[1]), "+f"(c[2]), "+f"(c[3])
        : "r"(a0), "r"(a1), "r"(a2), "r"(a3), "r"(b0), "r"(b1));
}

__device__ __forceinline__ void cp16(uint32_t dst_smem, const void* src) {
    asm volatile("cp.async.cg.shared.global [%0], [%1], 16;"
                 :: "r"(dst_smem), "l"(src));
}
#define CP_COMMIT()   asm volatile("cp.async.commit_group;" ::: "memory")
#define CP_WAIT_ALL() asm volatile("cp.async.wait_all;" ::: "memory")

// ---------------------------------------------------------------------------
// Prologue 1: convert fp32 inputs Q,K,V -> fp16
// ---------------------------------------------------------------------------
__global__ __launch_bounds__(256) void cvt3(
    const float* __restrict__ Q, const float* __restrict__ K,
    const float* __restrict__ V)
{
    const float* src = (blockIdx.y == 0) ? Q : (blockIdx.y == 1) ? K : V;
    __half* dst = (blockIdx.y == 0) ? hQ : (blockIdx.y == 1) ? hK : hV;
    int i = blockIdx.x * 256 + threadIdx.x;
    float4 a = ((const float4*)src)[2 * i];
    float4 b = ((const float4*)src)[2 * i + 1];
    uint4 w = make_uint4(f2h2(a.x, a.y), f2h2(a.z, a.w),
                         f2h2(b.x, b.y), f2h2(b.z, b.w));
    ((uint4*)dst)[i] = w;
}

// ---------------------------------------------------------------------------
// Prologue 2: pack weights: P[kp*DM + n] = {W[2kp][n], W[2kp+1][n]} fp16x2
// ---------------------------------------------------------------------------
__global__ __launch_bounds__(256) void packw(
    const float* __restrict__ Wq, const float* __restrict__ Wk,
    const float* __restrict__ Wv, const float* __restrict__ Wo)
{
    const float* W = (blockIdx.y == 0) ? Wq : (blockIdx.y == 1) ? Wk :
                     (blockIdx.y == 2) ? Wv : Wo;
    uint32_t* P = (blockIdx.y == 0) ? pWq : (blockIdx.y == 1) ? pWk :
                  (blockIdx.y == 2) ? pWv : pWo;
    int i = blockIdx.x * 256 + threadIdx.x;
    int kp = i / DM, n = i - kp * DM;
    P[i] = f2h2(W[(size_t)(2 * kp) * DM + n], W[(size_t)(2 * kp + 1) * DM + n]);
}

// ---------------------------------------------------------------------------
// GEMM fp16, mt=4: block tile 256x64, Ktile 32, 128 thr = 4 warps x (64m,64n).
// cp.async double-buffered. mode: 0 fp16 out (xoscale), 1 fp16 transposed, 2 f32+bias.
// ---------------------------------------------------------------------------
#define GA_ST 20
#define GB_ST 72
#define GBUF  (256 * GA_ST + 16 * GB_ST)
#define GEMM_SMEM (2 * GBUF * 4)                // 50176 B

__device__ __forceinline__ void gemm16_body(
    const __half* __restrict__ A, const uint32_t* __restrict__ Bp,
    const float* __restrict__ bias, void* __restrict__ Cout,
    int bx, int by, int mode, float oscale)
{
    extern __shared__ uint32_t sm[];
    const uint32_t sb = (uint32_t)__cvta_generic_to_shared(sm);

    const int tid  = threadIdx.x;
    const int warp = tid >> 5, lane = tid & 31;
    const int g = lane >> 2, tg = lane & 3;
    const int m0 = by * 256, n0 = bx * 64;
    const int wbase = warp * 64;

    float acc[4][8][4];
#pragma unroll
    for (int mt = 0; mt < 4; mt++)
#pragma unroll
        for (int nt = 0; nt < 8; nt++)
#pragma unroll
            for (int c = 0; c < 4; c++) acc[mt][nt][c] = 0.f;

    auto issue = [&](int t, int b) {
        uint32_t base = sb + (uint32_t)(b * GBUF) * 4;
#pragma unroll
        for (int it = 0; it < 8; it++) {
            int idx = it * 128 + tid;
            int r = idx >> 2, c16 = idx & 3;
            cp16(base + (uint32_t)(r * GA_ST + c16 * 4) * 4,
                 &A[(size_t)(m0 + r) * DM + t * 32 + c16 * 8]);
        }
#pragma unroll
        for (int it = 0; it < 2; it++) {
            int idx = it * 128 + tid;
            int kp = idx >> 4, nc = idx & 15;
            cp16(base + (uint32_t)(256 * GA_ST + kp * GB_ST + nc * 4) * 4,
                 &Bp[(size_t)(t * 16 + kp) * DM + n0 + nc * 4]);
        }
        CP_COMMIT();
    };

    issue(0, 0);

    const int NT = DM / 32;   // 24
    for (int t = 0; t < NT; t++) {
        CP_WAIT_ALL();
        __syncthreads();
        if (t + 1 < NT) issue(t + 1, (t + 1) & 1);

        const uint32_t* Ab = sm + (t & 1) * GBUF;
        const uint32_t* Bb = Ab + 256 * GA_ST;

#pragma unroll
        for (int c = 0; c < 2; c++) {
            int kcw = c * 8 + tg;
            uint32_t a[4][4];
#pragma unroll
            for (int mt = 0; mt < 4; mt++) {
                int r = wbase + mt * 16 + g;
                a[mt][0] = Ab[r * GA_ST + kcw];
                a[mt][1] = Ab[(r + 8) * GA_ST + kcw];
                a[mt][2] = Ab[r * GA_ST + kcw + 4];
                a[mt][3] = Ab[(r + 8) * GA_ST + kcw + 4];
            }
#pragma unroll
            for (int nt = 0; nt < 8; nt++) {
                int cn = nt * 8 + g;
                uint32_t b0 = Bb[kcw * GB_ST + cn];
                uint32_t b1 = Bb[(kcw + 4) * GB_ST + cn];
#pragma unroll
                for (int mt = 0; mt < 4; mt++)
                    mma_f16(acc[mt][nt], a[mt][0], a[mt][1], a[mt][2], a[mt][3],
                            b0, b1);
            }
        }
        __syncthreads();
    }

    if (mode == 0) {
        uint32_t* out = (uint32_t*)Cout;
#pragma unroll
        for (int mt = 0; mt < 4; mt++)
#pragma unroll
            for (int nt = 0; nt < 8; nt++) {
                int r = m0 + wbase + mt * 16 + g;
                int c = n0 + nt * 8 + 2 * tg;
                out[((size_t)r * DM + c) >> 1] =
                    f2h2(acc[mt][nt][0] * oscale, acc[mt][nt][1] * oscale);
                out[((size_t)(r + 8) * DM + c) >> 1] =
                    f2h2(acc[mt][nt][2] * oscale, acc[mt][nt][3] * oscale);
            }
    } else if (mode == 1) {
        __half* out = (__half*)Cout;
#pragma unroll
        for (int mt = 0; mt < 4; mt++)
#pragma unroll
            for (int nt = 0; nt < 8; nt++) {
                int r = m0 + wbase + mt * 16 + g;
                int c = n0 + nt * 8 + 2 * tg;
                out[(size_t)c * S_LEN + r]           = __float2half_rn(acc[mt][nt][0]);
                out[(size_t)(c + 1) * S_LEN + r]     = __float2half_rn(acc[mt][nt][1]);
                out[(size_t)c * S_LEN + r + 8]       = __float2half_rn(acc[mt][nt][2]);
                out[(size_t)(c + 1) * S_LEN + r + 8] = __float2half_rn(acc[mt][nt][3]);
            }
    } else {
        float* out = (float*)Cout;
#pragma unroll
        for (int mt = 0; mt < 4; mt++)
#pragma unroll
            for (int nt = 0; nt < 8; nt++) {
                int r = m0 + wbase + mt * 16 + g;
                int c = n0 + nt * 8 + 2 * tg;
                float b0 = bias[c], b1 = bias[c + 1];
                *(float2*)&out[(size_t)r * DM + c] =
                    make_float2(acc[mt][nt][0] + b0, acc[mt][nt][1] + b1);
                *(float2*)&out[(size_t)(r + 8) * DM + c] =
                    make_float2(acc[mt][nt][2] + b0, acc[mt][nt][3] + b1);
            }
    }
}

__global__ __launch_bounds__(128) void proj3(float* dummy) {
    if (blockIdx.z == 0)
        gemm16_body(hQ, pWq, nullptr, g_q16, blockIdx.x, blockIdx.y, 0, QSCALE);
    else if (blockIdx.z == 1)
        gemm16_body(hK, pWk, nullptr, g_k16, blockIdx.x, blockIdx.y, 0, 1.f);
    else
        gemm16_body(hV, pWv, nullptr, g_vT, blockIdx.x, blockIdx.y, 1, 1.f);
}

__global__ __launch_bounds__(128) void outg(const float* bias, float* out) {
    gemm16_body(g_a16, pWo, bias, out, blockIdx.x, blockIdx.y, 2, 1.f);
}

// ---------------------------------------------------------------------------
// Flash attention fp16: 128 q-rows x 1 head, 128 thr (4 warps x 32 rows).
// Scores in log2-domain (Q prescaled). exp via ex2.approx.f16x2 producing the
// PV A-fragments directly. Row-sums (l) via mma against constant ones-B.
// ---------------------------------------------------------------------------
#define KT_ST 36
#define ABUF  (2 * 64 * KT_ST)

__global__ __launch_bounds__(128, 2) void attn16(float* dummy)
{
    __shared__ uint32_t sm[2 * ABUF];   // 36864 B
    const uint32_t sb = (uint32_t)__cvta_generic_to_shared(sm);

    const int h = blockIdx.y;
    const int t = blockIdx.x;
    const int iq = (t & 1) ? (31 - (t >> 1)) : (t >> 1);
    const int tid = threadIdx.x, warp = tid >> 5, lane = tid & 31;
    const int g = lane >> 2, tg = lane & 3;
    const int hoff = h * HD;
    const int wbase = warp * 32;
    const int qrow0 = iq * 128 + wbase + g;

    // Q fragments from gmem fp16 (pre-scaled by QSCALE)
    const uint32_t* qw = (const uint32_t*)g_q16;
    uint32_t qf[2][4][4];
#pragma unroll
    for (int mt = 0; mt < 2; mt++) {
        size_t b0 = ((size_t)(qrow0 + mt * 16) * DM + hoff) >> 1;
        size_t b1 = ((size_t)(qrow0 + mt * 16 + 8) * DM + hoff) >> 1;
#pragma unroll
        for (int c = 0; c < 4; c++) {
            qf[mt][c][0] = qw[b0 + c * 8 + tg];
            qf[mt][c][1] = qw[b1 + c * 8 + tg];
            qf[mt][c][2] = qw[b0 + c * 8 + tg + 4];
            qf[mt][c][3] = qw[b1 + c * 8 + tg + 4];
        }
    }

    float of[2][8][4];
#pragma unroll
    for (int mt = 0; mt < 2; mt++)
#pragma unroll
        for (int nt = 0; nt < 8; nt++)
#pragma unroll
            for (int c = 0; c < 4; c++) of[mt][nt][c] = 0.f;
    float mrow[2][2], lrow[2][2];
#pragma unroll
    for (int mt = 0; mt < 2; mt++) {
        mrow[mt][0] = mrow[mt][1] = -1e30f;
        lrow[mt][0] = lrow[mt][1] = 0.f;
    }

    auto issue = [&](int kt, int b) {
        uint32_t base = sb + (uint32_t)(b * ABUF) * 4;
#pragma unroll
        for (int it = 0; it < 4; it++) {
            int idx = it * 128 + tid;
            int r = idx >> 3, c16 = idx & 7;
            cp16(base + (uint32_t)(r * KT_ST + c16 * 4) * 4,
                 &g_k16[(size_t)(kt * 64 + r) * DM + hoff + c16 * 8]);
            cp16(base + (uint32_t)(64 * KT_ST + r * KT_ST + c16 * 4) * 4,
                 &g_vT[(size_t)(hoff + r) * S_LEN + kt * 64 + c16 * 8]);
        }
        CP_COMMIT();
    };

    issue(0, 0);

    const int ktmax = 2 * iq + 1;
    for (int kt = 0; kt <= ktmax; kt++) {
        CP_WAIT_ALL();
        __syncthreads();
        if (kt < ktmax) issue(kt + 1, (kt + 1) & 1);

        const uint32_t* Kb = sm + (kt & 1) * ABUF;
        const uint32_t* Vb = Kb + 64 * KT_ST;

        // S = Q @ K^T  (log2-domain scores)
        float s[2][8][4];
#pragma unroll
        for (int mt = 0; mt < 2; mt++)
#pragma unroll
            for (int nt = 0; nt < 8; nt++)
#pragma unroll
                for (int c = 0; c < 4; c++) s[mt][nt][c] = 0.f;

#pragma unroll
        for (int c = 0; c < 4; c++) {
            int kcw = c * 8 + tg;
#pragma unroll
            for (int nt = 0; nt < 8; nt++) {
                int krow = nt * 8 + g;
                uint32_t b0 = Kb[krow * KT_ST + kcw];
                uint32_t b1 = Kb[krow * KT_ST + kcw + 4];
                mma_f16(s[0][nt], qf[0][c][0], qf[0][c][1], qf[0][c][2], qf[0][c][3], b0, b1);
                mma_f16(s[1][nt], qf[1][c][0], qf[1][c][1], qf[1][c][2], qf[1][c][3], b0, b1);
            }
        }

        // causal mask (no scale — folded into Q)
        const bool need_mask = (kt >= 2 * iq);
        if (need_mask) {
#pragma unroll
            for (int mt = 0; mt < 2; mt++) {
                int r0 = qrow0 + mt * 16;
#pragma unroll
                for (int nt = 0; nt < 8; nt++) {
                    int col = kt * 64 + nt * 8 + 2 * tg;
                    if (col     > r0)     s[mt][nt][0] = -1e30f;
                    if (col + 1 > r0)     s[mt][nt][1] = -1e30f;
                    if (col     > r0 + 8) s[mt][nt][2] = -1e30f;
                    if (col + 1 > r0 + 8) s[mt][nt][3] = -1e30f;
                }
            }
        }

        // online softmax: max + rescale (sum comes from the ones-mma below)
        uint32_t ah[2][4][4];
#pragma unroll
        for (int mt = 0; mt < 2; mt++) {
            float rm0 = -1e30f, rm1 = -1e30f;
#pragma unroll
            for (int nt = 0; nt < 8; nt++) {
                rm0 = fmaxf(rm0, fmaxf(s[mt][nt][0], s[mt][nt][1]));
                rm1 = fmaxf(rm1, fmaxf(s[mt][nt][2], s[mt][nt][3]));
            }
#pragma unroll
            for (int off = 1; off <= 2; off <<= 1) {
                rm0 = fmaxf(rm0, __shfl_xor_sync(0xFFFFFFFFu, rm0, off));
                rm1 = fmaxf(rm1, __shfl_xor_sync(0xFFFFFFFFu, rm1, off));
            }
            float nm0 = fmaxf(mrow[mt][0], rm0), nm1 = fmaxf(mrow[mt][1], rm1);
            float al0 = exp2f(mrow[mt][0] - nm0), al1 = exp2f(mrow[mt][1] - nm1);
            mrow[mt][0] = nm0;  mrow[mt][1] = nm1;
            lrow[mt][0] *= al0; lrow[mt][1] *= al1;
#pragma unroll
            for (int nt = 0; nt < 8; nt++) {
                of[mt][nt][0] *= al0; of[mt][nt][1] *= al0;
                of[mt][nt][2] *= al1; of[mt][nt][3] *= al1;
            }

            // exp in fp16 pairs -> PV A-fragments directly
            uint32_t nm0p = f2h2(nm0, nm0), nm1p = f2h2(nm1, nm1);
#pragma unroll
            for (int c = 0; c < 4; c++) {
                ah[mt][c][0] = ex2h2(hsub2u(f2h2(s[mt][2*c][0],   s[mt][2*c][1]),   nm0p));
                ah[mt][c][1] = ex2h2(hsub2u(f2h2(s[mt][2*c][2],   s[mt][2*c][3]),   nm1p));
                ah[mt][c][2] = ex2h2(hsub2u(f2h2(s[mt][2*c+1][0], s[mt][2*c+1][1]), nm0p));
                ah[mt][c][3] = ex2h2(hsub2u(f2h2(s[mt][2*c+1][2], s[mt][2*c+1][3]), nm1p));
            }
        }

        // O += P @ V, plus row-sums via ones-B mma (exact-P consistency)
        float sacc[2][4];
#pragma unroll
        for (int mt = 0; mt < 2; mt++)
#pragma unroll
            for (int c = 0; c < 4; c++) sacc[mt][c] = 0.f;

#pragma unroll
        for (int c = 0; c < 4; c++) {
            int kcw = c * 8 + tg;
#pragma unroll
            for (int nt = 0; nt < 8; nt++) {
                int dvr = nt * 8 + g;
                uint32_t b0 = Vb[dvr * KT_ST + kcw];
                uint32_t b1 = Vb[(dvr)*KT_ST + kcw + 4];
                mma_f16(of[0][nt], ah[0][c][0], ah[0][c][1], ah[0][c][2], ah[0][c][3], b0, b1);
                mma_f16(of[1][nt], ah[1][c][0], ah[1][c][1], ah[1][c][2], ah[1][c][3], b0, b1);
            }
            mma_f16(sacc[0], ah[0][c][0], ah[0][c][1], ah[0][c][2], ah[0][c][3], ONESH2, ONESH2);
            mma_f16(sacc[1], ah[1][c][0], ah[1][c][1], ah[1][c][2], ah[1][c][3], ONESH2, ONESH2);
        }
#pragma unroll
        for (int mt = 0; mt < 2; mt++) {
            lrow[mt][0] += sacc[mt][0];
            lrow[mt][1] += sacc[mt][2];
        }
    }

    // epilogue -> fp16 att buffer
    uint32_t* out = (uint32_t*)g_a16;
#pragma unroll
    for (int mt = 0; mt < 2; mt++) {
        float inv0 = 1.f / lrow[mt][0], inv1 = 1.f / lrow[mt][1];
        int r0 = qrow0 + mt * 16;
#pragma unroll
        for (int nt = 0; nt < 8; nt++) {
            int c = hoff + nt * 8 + 2 * tg;
            out[((size_t)r0 * DM + c) >> 1] =
                f2h2(of[mt][nt][0] * inv0, of[mt][nt][1] * inv0);
            out[((size_t)(r0 + 8) * DM + c) >> 1] =
                f2h2(of[mt][nt][2] * inv1, of[mt][nt][3] * inv1);
        }
    }
}

// ---------------------------------------------------------------------------
// Launch
// ---------------------------------------------------------------------------
extern "C" void kernel_launch(void* const* d_in, const int* in_sizes, int n_in,
                              void* d_out, int out_size)
{
    const float* Q  = (const float*)d_in[0];
    const float* K  = (const float*)d_in[1];
    const float* V  = (const float*)d_in[2];
    const float* Wq = (const float*)d_in[3];
    const float* Wk = (const float*)d_in[4];
    const float* Wv = (const float*)d_in[5];
    const float* Wo = (const float*)d_in[6];
    const float* bo = (const float*)d_in[7];
    float* out = (float*)d_out;

    static bool attr_set = false;
    if (!attr_set) {
        cudaFuncSetAttribute(proj3, cudaFuncAttributeMaxDynamicSharedMemorySize,
                             GEMM_SMEM);
        cudaFuncSetAttribute(outg, cudaFuncAttributeMaxDynamicSharedMemorySize,
                             GEMM_SMEM);
        attr_set = true;
    }

    cvt3<<<dim3(S_LEN * DM / 8 / 256, 3), 256>>>(Q, K, V);
    packw<<<dim3(KW * DM / 256, 4), 256>>>(Wq, Wk, Wv, Wo);

    proj3<<<dim3(DM / 64, S_LEN / 256, 3), 128, GEMM_SMEM>>>(nullptr);

    attn16<<<dim3(S_LEN / 128, NH), 128>>>(nullptr);

    outg<<<dim3(DM / 64, S_LEN / 256), 128, GEMM_SMEM>>>(bo, out);
}

// round 14
// speedup vs baseline: 1.9343x; 1.0075x over previous
#include <cuda_runtime.h>
#include <cuda_fp16.h>
#include <stdint.h>

#define S_LEN 4096
#define DM    768
#define NH    12
#define HD    64
#define KW    (DM / 2)

// Q prescale: 0.125 (1/sqrt(64)) * log2(e) -> scores in log2 domain
#define QSCALE 0.18033688011112042f
#define ONESH2 0x3C003C00u   // fp16x2 {1.0, 1.0}

__device__ __align__(16) __half   hQ[S_LEN * DM], hK[S_LEN * DM], hV[S_LEN * DM];
__device__ __align__(16) uint32_t pWq[KW * DM], pWk[KW * DM], pWv[KW * DM], pWo[KW * DM];
__device__ __align__(16) __half   g_q16[S_LEN * DM];
__device__ __align__(16) __half   g_k16[S_LEN * DM];
__device__ __align__(16) __half   g_vT [DM * S_LEN];   // [h*64+dv][key]
__device__ __align__(16) __half   g_a16[S_LEN * DM];

__device__ __forceinline__ uint32_t f2h2(float lo, float hi) {
    uint32_t r;
    asm("cvt.rn.f16x2.f32 %0, %1, %2;" : "=r"(r) : "f"(hi), "f"(lo));
    return r;
}
__device__ __forceinline__ uint32_t hsub2u(uint32_t a, uint32_t b) {
    uint32_t r;
    asm("sub.rn.f16x2 %0, %1, %2;" : "=r"(r) : "r"(a), "r"(b));
    return r;
}
__device__ __forceinline__ uint32_t ex2h2(uint32_t x) {
    uint32_t r;
    asm("ex2.approx.f16x2 %0, %1;" : "=r"(r) : "r"(x));
    return r;
}
__device__ __forceinline__ void mma_f16(float c[4],
    uint32_t a0, uint32_t a1, uint32_t a2, uint32_t a3,
    uint32_t b0, uint32_t b1)
{
    asm volatile(
        "mma.sync.aligned.m16n8k16.row.col.f32.f16.f16.f32 "
        "{%0,%1,%2,%3}, {%4,%5,%6,%7}, {%8,%9}, {%0,%1,%2,%3};"
        : "+f"(c[0]), "+f"(c[1]), "+f"(c[2]), "+f"(c[3])
        : "r"(a0), "r"(a1), "r"(a2), "r"(a3), "r"(b0), "r"(b1));
}
__device__ __forceinline__ void cp16(uint32_t dst_smem, const void* src) {
    asm volatile("cp.async.cg.shared.global [%0], [%1], 16;"
                 :: "r"(dst_smem), "l"(src));
}
#define CP_COMMIT()   asm volatile("cp.async.commit_group;" ::: "memory")
#define CP_WAIT_ALL() asm volatile("cp.async.wait_all;" ::: "memory")

// ---------------------------------------------------------------------------
// Prologues
// ---------------------------------------------------------------------------
__global__ __launch_bounds__(256) void cvt3(
    const float* __restrict__ Q, const float* __restrict__ K,
    const float* __restrict__ V)
{
    const float* src = (blockIdx.y == 0) ? Q : (blockIdx.y == 1) ? K : V;
    __half* dst = (blockIdx.y == 0) ? hQ : (blockIdx.y == 1) ? hK : hV;
    int i = blockIdx.x * 256 + threadIdx.x;
    float4 a = ((const float4*)src)[2 * i];
    float4 b = ((const float4*)src)[2 * i + 1];
    uint4 w = make_uint4(f2h2(a.x, a.y), f2h2(a.z, a.w),
                         f2h2(b.x, b.y), f2h2(b.z, b.w));
    ((uint4*)dst)[i] = w;
}

__global__ __launch_bounds__(256) void packw(
    const float* __restrict__ Wq, const float* __restrict__ Wk,
    const float* __restrict__ Wv, const float* __restrict__ Wo)
{
    const float* W = (blockIdx.y == 0) ? Wq : (blockIdx.y == 1) ? Wk :
                     (blockIdx.y == 2) ? Wv : Wo;
    uint32_t* P = (blockIdx.y == 0) ? pWq : (blockIdx.y == 1) ? pWk :
                  (blockIdx.y == 2) ? pWv : pWo;
    int i = blockIdx.x * 256 + threadIdx.x;
    int kp = i / DM, n = i - kp * DM;
    P[i] = f2h2(W[(size_t)(2 * kp) * DM + n], W[(size_t)(2 * kp + 1) * DM + n]);
}

// ---------------------------------------------------------------------------
// GEMM fp16 (unchanged, passing at round 12)
// ---------------------------------------------------------------------------
#define GA_ST 20
#define GB_ST 72
#define GBUF  (256 * GA_ST + 16 * GB_ST)
#define GEMM_SMEM (2 * GBUF * 4)

__device__ __forceinline__ void gemm16_body(
    const __half* __restrict__ A, const uint32_t* __restrict__ Bp,
    const float* __restrict__ bias, void* __restrict__ Cout,
    int bx, int by, int mode, float oscale)
{
    extern __shared__ uint32_t sm[];
    const uint32_t sb = (uint32_t)__cvta_generic_to_shared(sm);

    const int tid  = threadIdx.x;
    const int warp = tid >> 5, lane = tid & 31;
    const int g = lane >> 2, tg = lane & 3;
    const int m0 = by * 256, n0 = bx * 64;
    const int wbase = warp * 64;

    float acc[4][8][4];
#pragma unroll
    for (int mt = 0; mt < 4; mt++)
#pragma unroll
        for (int nt = 0; nt < 8; nt++)
#pragma unroll
            for (int c = 0; c < 4; c++) acc[mt][nt][c] = 0.f;

    auto issue = [&](int t, int b) {
        uint32_t base = sb + (uint32_t)(b * GBUF) * 4;
#pragma unroll
        for (int it = 0; it < 8; it++) {
            int idx = it * 128 + tid;
            int r = idx >> 2, c16 = idx & 3;
            cp16(base + (uint32_t)(r * GA_ST + c16 * 4) * 4,
                 &A[(size_t)(m0 + r) * DM + t * 32 + c16 * 8]);
        }
#pragma unroll
        for (int it = 0; it < 2; it++) {
            int idx = it * 128 + tid;
            int kp = idx >> 4, nc = idx & 15;
            cp16(base + (uint32_t)(256 * GA_ST + kp * GB_ST + nc * 4) * 4,
                 &Bp[(size_t)(t * 16 + kp) * DM + n0 + nc * 4]);
        }
        CP_COMMIT();
    };

    issue(0, 0);

    const int NT = DM / 32;
    for (int t = 0; t < NT; t++) {
        CP_WAIT_ALL();
        __syncthreads();
        if (t + 1 < NT) issue(t + 1, (t + 1) & 1);

        const uint32_t* Ab = sm + (t & 1) * GBUF;
        const uint32_t* Bb = Ab + 256 * GA_ST;

#pragma unroll
        for (int c = 0; c < 2; c++) {
            int kcw = c * 8 + tg;
            uint32_t a[4][4];
#pragma unroll
            for (int mt = 0; mt < 4; mt++) {
                int r = wbase + mt * 16 + g;
                a[mt][0] = Ab[r * GA_ST + kcw];
                a[mt][1] = Ab[(r + 8) * GA_ST + kcw];
                a[mt][2] = Ab[r * GA_ST + kcw + 4];
                a[mt][3] = Ab[(r + 8) * GA_ST + kcw + 4];
            }
#pragma unroll
            for (int nt = 0; nt < 8; nt++) {
                int cn = nt * 8 + g;
                uint32_t b0 = Bb[kcw * GB_ST + cn];
                uint32_t b1 = Bb[(kcw + 4) * GB_ST + cn];
#pragma unroll
                for (int mt = 0; mt < 4; mt++)
                    mma_f16(acc[mt][nt], a[mt][0], a[mt][1], a[mt][2], a[mt][3],
                            b0, b1);
            }
        }
        __syncthreads();
    }

    if (mode == 0) {
        uint32_t* out = (uint32_t*)Cout;
#pragma unroll
        for (int mt = 0; mt < 4; mt++)
#pragma unroll
            for (int nt = 0; nt < 8; nt++) {
                int r = m0 + wbase + mt * 16 + g;
                int c = n0 + nt * 8 + 2 * tg;
                out[((size_t)r * DM + c) >> 1] =
                    f2h2(acc[mt][nt][0] * oscale, acc[mt][nt][1] * oscale);
                out[((size_t)(r + 8) * DM + c) >> 1] =
                    f2h2(acc[mt][nt][2] * oscale, acc[mt][nt][3] * oscale);
            }
    } else if (mode == 1) {
        __half* out = (__half*)Cout;
#pragma unroll
        for (int mt = 0; mt < 4; mt++)
#pragma unroll
            for (int nt = 0; nt < 8; nt++) {
                int r = m0 + wbase + mt * 16 + g;
                int c = n0 + nt * 8 + 2 * tg;
                out[(size_t)c * S_LEN + r]           = __float2half_rn(acc[mt][nt][0]);
                out[(size_t)(c + 1) * S_LEN + r]     = __float2half_rn(acc[mt][nt][1]);
                out[(size_t)c * S_LEN + r + 8]       = __float2half_rn(acc[mt][nt][2]);
                out[(size_t)(c + 1) * S_LEN + r + 8] = __float2half_rn(acc[mt][nt][3]);
            }
    } else {
        float* out = (float*)Cout;
#pragma unroll
        for (int mt = 0; mt < 4; mt++)
#pragma unroll
            for (int nt = 0; nt < 8; nt++) {
                int r = m0 + wbase + mt * 16 + g;
                int c = n0 + nt * 8 + 2 * tg;
                float b0 = bias[c], b1 = bias[c + 1];
                *(float2*)&out[(size_t)r * DM + c] =
                    make_float2(acc[mt][nt][0] + b0, acc[mt][nt][1] + b1);
                *(float2*)&out[(size_t)(r + 8) * DM + c] =
                    make_float2(acc[mt][nt][2] + b0, acc[mt][nt][3] + b1);
            }
    }
}

__global__ __launch_bounds__(128) void proj3(float* dummy) {
    if (blockIdx.z == 0)
        gemm16_body(hQ, pWq, nullptr, g_q16, blockIdx.x, blockIdx.y, 0, QSCALE);
    else if (blockIdx.z == 1)
        gemm16_body(hK, pWk, nullptr, g_k16, blockIdx.x, blockIdx.y, 0, 1.f);
    else
        gemm16_body(hV, pWv, nullptr, g_vT, blockIdx.x, blockIdx.y, 1, 1.f);
}

__global__ __launch_bounds__(128) void outg(const float* bias, float* out) {
    gemm16_body(g_a16, pWo, bias, out, blockIdx.x, blockIdx.y, 2, 1.f);
}

// ---------------------------------------------------------------------------
// Flash attention fp16: 64 q-rows x 1 head, 128 thr (4 warps x 16 rows),
// 3 blocks/SM. Log2-domain scores; ex2.approx.f16x2 -> PV A-frags;
// row-sums via ones-mma; cp.async double-buffer.
// ---------------------------------------------------------------------------
#define KT_ST 36
#define ABUF  (2 * 64 * KT_ST)

__global__ __launch_bounds__(128, 3) void attn16(float* dummy)
{
    __shared__ uint32_t sm[2 * ABUF];   // 36864 B
    const uint32_t sb = (uint32_t)__cvta_generic_to_shared(sm);

    const int h = blockIdx.y;
    const int t = blockIdx.x;
    const int iq = (t & 1) ? (63 - (t >> 1)) : (t >> 1);  // heavy/light interleave
    const int tid = threadIdx.x, warp = tid >> 5, lane = tid & 31;
    const int g = lane >> 2, tg = lane & 3;
    const int hoff = h * HD;
    const int qrow0 = iq * 64 + warp * 16 + g;   // rows qrow0, qrow0+8

    // Q fragments from gmem fp16 (pre-scaled by QSCALE)
    const uint32_t* qw = (const uint32_t*)g_q16;
    uint32_t qf[4][4];
    {
        size_t b0 = ((size_t)qrow0 * DM + hoff) >> 1;
        size_t b1 = ((size_t)(qrow0 + 8) * DM + hoff) >> 1;
#pragma unroll
        for (int c = 0; c < 4; c++) {
            qf[c][0] = qw[b0 + c * 8 + tg];
            qf[c][1] = qw[b1 + c * 8 + tg];
            qf[c][2] = qw[b0 + c * 8 + tg + 4];
            qf[c][3] = qw[b1 + c * 8 + tg + 4];
        }
    }

    float of[8][4];
#pragma unroll
    for (int nt = 0; nt < 8; nt++)
#pragma unroll
        for (int c = 0; c < 4; c++) of[nt][c] = 0.f;
    float m0r = -1e30f, m1r = -1e30f, l0 = 0.f, l1 = 0.f;

    auto issue = [&](int kt, int b) {
        uint32_t base = sb + (uint32_t)(b * ABUF) * 4;
#pragma unroll
        for (int it = 0; it < 4; it++) {
            int idx = it * 128 + tid;
            int r = idx >> 3, c16 = idx & 7;
            cp16(base + (uint32_t)(r * KT_ST + c16 * 4) * 4,
                 &g_k16[(size_t)(kt * 64 + r) * DM + hoff + c16 * 8]);
            cp16(base + (uint32_t)(64 * KT_ST + r * KT_ST + c16 * 4) * 4,
                 &g_vT[(size_t)(hoff + r) * S_LEN + kt * 64 + c16 * 8]);
        }
        CP_COMMIT();
    };

    issue(0, 0);

    const int ktmax = iq;
    for (int kt = 0; kt <= ktmax; kt++) {
        CP_WAIT_ALL();
        __syncthreads();
        if (kt < ktmax) issue(kt + 1, (kt + 1) & 1);

        const uint32_t* Kb = sm + (kt & 1) * ABUF;
        const uint32_t* Vb = Kb + 64 * KT_ST;

        // S = Q @ K^T (log2-domain)
        float s[8][4];
#pragma unroll
        for (int nt = 0; nt < 8; nt++)
#pragma unroll
            for (int c = 0; c < 4; c++) s[nt][c] = 0.f;

#pragma unroll
        for (int c = 0; c < 4; c++) {
            int kcw = c * 8 + tg;
#pragma unroll
            for (int nt = 0; nt < 8; nt++) {
                int krow = nt * 8 + g;
                uint32_t b0 = Kb[krow * KT_ST + kcw];
                uint32_t b1 = Kb[krow * KT_ST + kcw + 4];
                mma_f16(s[nt], qf[c][0], qf[c][1], qf[c][2], qf[c][3], b0, b1);
            }
        }

        // causal mask only on the diagonal tile
        if (kt == iq) {
#pragma unroll
            for (int nt = 0; nt < 8; nt++) {
                int col = kt * 64 + nt * 8 + 2 * tg;
                if (col     > qrow0)     s[nt][0] = -1e30f;
                if (col + 1 > qrow0)     s[nt][1] = -1e30f;
                if (col     > qrow0 + 8) s[nt][2] = -1e30f;
                if (col + 1 > qrow0 + 8) s[nt][3] = -1e30f;
            }
        }

        // online softmax: max + rescale
        float rm0 = -1e30f, rm1 = -1e30f;
#pragma unroll
        for (int nt = 0; nt < 8; nt++) {
            rm0 = fmaxf(rm0, fmaxf(s[nt][0], s[nt][1]));
            rm1 = fmaxf(rm1, fmaxf(s[nt][2], s[nt][3]));
        }
#pragma unroll
        for (int off = 1; off <= 2; off <<= 1) {
            rm0 = fmaxf(rm0, __shfl_xor_sync(0xFFFFFFFFu, rm0, off));
            rm1 = fmaxf(rm1, __shfl_xor_sync(0xFFFFFFFFu, rm1, off));
        }
        float nm0 = fmaxf(m0r, rm0), nm1 = fmaxf(m1r, rm1);
        float al0 = exp2f(m0r - nm0), al1 = exp2f(m1r - nm1);
        m0r = nm0;  m1r = nm1;
        l0 *= al0;  l1 *= al1;
#pragma unroll
        for (int nt = 0; nt < 8; nt++) {
            of[nt][0] *= al0; of[nt][1] *= al0;
            of[nt][2] *= al1; of[nt][3] *= al1;
        }

        // exp in fp16 pairs -> PV A-fragments directly
        uint32_t ah[4][4];
        uint32_t nm0p = f2h2(nm0, nm0), nm1p = f2h2(nm1, nm1);
#pragma unroll
        for (int c = 0; c < 4; c++) {
            ah[c][0] = ex2h2(hsub2u(f2h2(s[2*c][0],   s[2*c][1]),   nm0p));
            ah[c][1] = ex2h2(hsub2u(f2h2(s[2*c][2],   s[2*c][3]),   nm1p));
            ah[c][2] = ex2h2(hsub2u(f2h2(s[2*c+1][0], s[2*c+1][1]), nm0p));
            ah[c][3] = ex2h2(hsub2u(f2h2(s[2*c+1][2], s[2*c+1][3]), nm1p));
        }

        // O += P @ V, plus row-sums via ones-mma
        float sacc[4] = {0.f, 0.f, 0.f, 0.f};
#pragma unroll
        for (int c = 0; c < 4; c++) {
            int kcw = c * 8 + tg;
#pragma unroll
            for (int nt = 0; nt < 8; nt++) {
                int dvr = nt * 8 + g;
                uint32_t b0 = Vb[dvr * KT_ST + kcw];
                uint32_t b1 = Vb[dvr * KT_ST + kcw + 4];
                mma_f16(of[nt], ah[c][0], ah[c][1], ah[c][2], ah[c][3], b0, b1);
            }
            mma_f16(sacc, ah[c][0], ah[c][1], ah[c][2], ah[c][3], ONESH2, ONESH2);
        }
        l0 += sacc[0];
        l1 += sacc[2];
    }

    // epilogue -> fp16 att buffer
    uint32_t* out = (uint32_t*)g_a16;
    float inv0 = 1.f / l0, inv1 = 1.f / l1;
#pragma unroll
    for (int nt = 0; nt < 8; nt++) {
        int c = hoff + nt * 8 + 2 * tg;
        out[((size_t)qrow0 * DM + c) >> 1] =
            f2h2(of[nt][0] * inv0, of[nt][1] * inv0);
        out[((size_t)(qrow0 + 8) * DM + c) >> 1] =
            f2h2(of[nt][2] * inv1, of[nt][3] * inv1);
    }
}

// ---------------------------------------------------------------------------
// Launch
// ---------------------------------------------------------------------------
extern "C" void kernel_launch(void* const* d_in, const int* in_sizes, int n_in,
                              void* d_out, int out_size)
{
    const float* Q  = (const float*)d_in[0];
    const float* K  = (const float*)d_in[1];
    const float* V  = (const float*)d_in[2];
    const float* Wq = (const float*)d_in[3];
    const float* Wk = (const float*)d_in[4];
    const float* Wv = (const float*)d_in[5];
    const float* Wo = (const float*)d_in[6];
    const float* bo = (const float*)d_in[7];
    float* out = (float*)d_out;

    static bool attr_set = false;
    if (!attr_set) {
        cudaFuncSetAttribute(proj3, cudaFuncAttributeMaxDynamicSharedMemorySize,
                             GEMM_SMEM);
        cudaFuncSetAttribute(outg, cudaFuncAttributeMaxDynamicSharedMemorySize,
                             GEMM_SMEM);
        attr_set = true;
    }

    cvt3<<<dim3(S_LEN * DM / 8 / 256, 3), 256>>>(Q, K, V);
    packw<<<dim3(KW * DM / 256, 4), 256>>>(Wq, Wk, Wv, Wo);

    proj3<<<dim3(DM / 64, S_LEN / 256, 3), 128, GEMM_SMEM>>>(nullptr);

    attn16<<<dim3(S_LEN / 64, NH), 128>>>(nullptr);

    outg<<<dim3(DM / 64, S_LEN / 256), 128, GEMM_SMEM>>>(bo, out);
}

// round 15
// speedup vs baseline: 2.0008x; 1.0344x over previous
#include <cuda_runtime.h>
#include <cuda_fp16.h>
#include <stdint.h>

#define S_LEN 4096
#define DM    768
#define NH    12
#define HD    64
#define KW    (DM / 2)

// Q prescale: 0.125 (1/sqrt(64)) * log2(e) -> scores in log2 domain
#define QSCALE 0.18033688011112042f
#define ONESH2 0x3C003C00u   // fp16x2 {1.0, 1.0}

__device__ __align__(16) __half   hQ[S_LEN * DM], hK[S_LEN * DM], hV[S_LEN * DM];
__device__ __align__(16) uint32_t pWq[KW * DM], pWk[KW * DM], pWv[KW * DM], pWo[KW * DM];
__device__ __align__(16) __half   g_q16[S_LEN * DM];
__device__ __align__(16) __half   g_k16[S_LEN * DM];
__device__ __align__(16) __half   g_vT [DM * S_LEN];   // [h*64+dv][key]
__device__ __align__(16) __half   g_a16[S_LEN * DM];

__device__ __forceinline__ uint32_t f2h2(float lo, float hi) {
    uint32_t r;
    asm("cvt.rn.f16x2.f32 %0, %1, %2;" : "=r"(r) : "f"(hi), "f"(lo));
    return r;
}
__device__ __forceinline__ uint32_t hsub2u(uint32_t a, uint32_t b) {
    uint32_t r;
    asm("sub.rn.f16x2 %0, %1, %2;" : "=r"(r) : "r"(a), "r"(b));
    return r;
}
__device__ __forceinline__ uint32_t ex2h2(uint32_t x) {
    uint32_t r;
    asm("ex2.approx.f16x2 %0, %1;" : "=r"(r) : "r"(x));
    return r;
}
__device__ __forceinline__ void mma_f16(float c[4],
    uint32_t a0, uint32_t a1, uint32_t a2, uint32_t a3,
    uint32_t b0, uint32_t b1)
{
    asm volatile(
        "mma.sync.aligned.m16n8k16.row.col.f32.f16.f16.f32 "
        "{%0,%1,%2,%3}, {%4,%5,%6,%7}, {%8,%9}, {%0,%1,%2,%3};"
        : "+f"(c[0]), "+f"(c[1]), "+f"(c[2]), "+f"(c[3])
        : "r"(a0), "r"(a1), "r"(a2), "r"(a3), "r"(b0), "r"(b1));
}
__device__ __forceinline__ void ldsm4(uint32_t& r0, uint32_t& r1,
                                      uint32_t& r2, uint32_t& r3, uint32_t addr)
{
    asm volatile("ldmatrix.sync.aligned.m8n8.x4.shared.b16 {%0,%1,%2,%3}, [%4];"
        : "=r"(r0), "=r"(r1), "=r"(r2), "=r"(r3) : "r"(addr));
}
__device__ __forceinline__ void cp16(uint32_t dst_smem, const void* src) {
    asm volatile("cp.async.cg.shared.global [%0], [%1], 16;"
                 :: "r"(dst_smem), "l"(src));
}
#define CP_COMMIT()   asm volatile("cp.async.commit_group;" ::: "memory")
#define CP_WAIT_ALL() asm volatile("cp.async.wait_all;" ::: "memory")

// ---------------------------------------------------------------------------
// Prologues (unchanged, passing)
// ---------------------------------------------------------------------------
__global__ __launch_bounds__(256) void cvt3(
    const float* __restrict__ Q, const float* __restrict__ K,
    const float* __restrict__ V)
{
    const float* src = (blockIdx.y == 0) ? Q : (blockIdx.y == 1) ? K : V;
    __half* dst = (blockIdx.y == 0) ? hQ : (blockIdx.y == 1) ? hK : hV;
    int i = blockIdx.x * 256 + threadIdx.x;
    float4 a = ((const float4*)src)[2 * i];
    float4 b = ((const float4*)src)[2 * i + 1];
    uint4 w = make_uint4(f2h2(a.x, a.y), f2h2(a.z, a.w),
                         f2h2(b.x, b.y), f2h2(b.z, b.w));
    ((uint4*)dst)[i] = w;
}

__global__ __launch_bounds__(256) void packw(
    const float* __restrict__ Wq, const float* __restrict__ Wk,
    const float* __restrict__ Wv, const float* __restrict__ Wo)
{
    const float* W = (blockIdx.y == 0) ? Wq : (blockIdx.y == 1) ? Wk :
                     (blockIdx.y == 2) ? Wv : Wo;
    uint32_t* P = (blockIdx.y == 0) ? pWq : (blockIdx.y == 1) ? pWk :
                  (blockIdx.y == 2) ? pWv : pWo;
    int i = blockIdx.x * 256 + threadIdx.x;
    int kp = i / DM, n = i - kp * DM;
    P[i] = f2h2(W[(size_t)(2 * kp) * DM + n], W[(size_t)(2 * kp + 1) * DM + n]);
}

// ---------------------------------------------------------------------------
// GEMM fp16 (unchanged, passing)
// ---------------------------------------------------------------------------
#define GA_ST 20
#define GB_ST 72
#define GBUF  (256 * GA_ST + 16 * GB_ST)
#define GEMM_SMEM (2 * GBUF * 4)

__device__ __forceinline__ void gemm16_body(
    const __half* __restrict__ A, const uint32_t* __restrict__ Bp,
    const float* __restrict__ bias, void* __restrict__ Cout,
    int bx, int by, int mode, float oscale)
{
    extern __shared__ uint32_t sm[];
    const uint32_t sb = (uint32_t)__cvta_generic_to_shared(sm);

    const int tid  = threadIdx.x;
    const int warp = tid >> 5, lane = tid & 31;
    const int g = lane >> 2, tg = lane & 3;
    const int m0 = by * 256, n0 = bx * 64;
    const int wbase = warp * 64;

    float acc[4][8][4];
#pragma unroll
    for (int mt = 0; mt < 4; mt++)
#pragma unroll
        for (int nt = 0; nt < 8; nt++)
#pragma unroll
            for (int c = 0; c < 4; c++) acc[mt][nt][c] = 0.f;

    auto issue = [&](int t, int b) {
        uint32_t base = sb + (uint32_t)(b * GBUF) * 4;
#pragma unroll
        for (int it = 0; it < 8; it++) {
            int idx = it * 128 + tid;
            int r = idx >> 2, c16 = idx & 3;
            cp16(base + (uint32_t)(r * GA_ST + c16 * 4) * 4,
                 &A[(size_t)(m0 + r) * DM + t * 32 + c16 * 8]);
        }
#pragma unroll
        for (int it = 0; it < 2; it++) {
            int idx = it * 128 + tid;
            int kp = idx >> 4, nc = idx & 15;
            cp16(base + (uint32_t)(256 * GA_ST + kp * GB_ST + nc * 4) * 4,
                 &Bp[(size_t)(t * 16 + kp) * DM + n0 + nc * 4]);
        }
        CP_COMMIT();
    };

    issue(0, 0);

    const int NT = DM / 32;
    for (int t = 0; t < NT; t++) {
        CP_WAIT_ALL();
        __syncthreads();
        if (t + 1 < NT) issue(t + 1, (t + 1) & 1);

        const uint32_t* Ab = sm + (t & 1) * GBUF;
        const uint32_t* Bb = Ab + 256 * GA_ST;

#pragma unroll
        for (int c = 0; c < 2; c++) {
            int kcw = c * 8 + tg;
            uint32_t a[4][4];
#pragma unroll
            for (int mt = 0; mt < 4; mt++) {
                int r = wbase + mt * 16 + g;
                a[mt][0] = Ab[r * GA_ST + kcw];
                a[mt][1] = Ab[(r + 8) * GA_ST + kcw];
                a[mt][2] = Ab[r * GA_ST + kcw + 4];
                a[mt][3] = Ab[(r + 8) * GA_ST + kcw + 4];
            }
#pragma unroll
            for (int nt = 0; nt < 8; nt++) {
                int cn = nt * 8 + g;
                uint32_t b0 = Bb[kcw * GB_ST + cn];
                uint32_t b1 = Bb[(kcw + 4) * GB_ST + cn];
#pragma unroll
                for (int mt = 0; mt < 4; mt++)
                    mma_f16(acc[mt][nt], a[mt][0], a[mt][1], a[mt][2], a[mt][3],
                            b0, b1);
            }
        }
        __syncthreads();
    }

    if (mode == 0) {
        uint32_t* out = (uint32_t*)Cout;
#pragma unroll
        for (int mt = 0; mt < 4; mt++)
#pragma unroll
            for (int nt = 0; nt < 8; nt++) {
                int r = m0 + wbase + mt * 16 + g;
                int c = n0 + nt * 8 + 2 * tg;
                out[((size_t)r * DM + c) >> 1] =
                    f2h2(acc[mt][nt][0] * oscale, acc[mt][nt][1] * oscale);
                out[((size_t)(r + 8) * DM + c) >> 1] =
                    f2h2(acc[mt][nt][2] * oscale, acc[mt][nt][3] * oscale);
            }
    } else if (mode == 1) {
        __half* out = (__half*)Cout;
#pragma unroll
        for (int mt = 0; mt < 4; mt++)
#pragma unroll
            for (int nt = 0; nt < 8; nt++) {
                int r = m0 + wbase + mt * 16 + g;
                int c = n0 + nt * 8 + 2 * tg;
                out[(size_t)c * S_LEN + r]           = __float2half_rn(acc[mt][nt][0]);
                out[(size_t)(c + 1) * S_LEN + r]     = __float2half_rn(acc[mt][nt][1]);
                out[(size_t)c * S_LEN + r + 8]       = __float2half_rn(acc[mt][nt][2]);
                out[(size_t)(c + 1) * S_LEN + r + 8] = __float2half_rn(acc[mt][nt][3]);
            }
    } else {
        float* out = (float*)Cout;
#pragma unroll
        for (int mt = 0; mt < 4; mt++)
#pragma unroll
            for (int nt = 0; nt < 8; nt++) {
                int r = m0 + wbase + mt * 16 + g;
                int c = n0 + nt * 8 + 2 * tg;
                float b0 = bias[c], b1 = bias[c + 1];
                *(float2*)&out[(size_t)r * DM + c] =
                    make_float2(acc[mt][nt][0] + b0, acc[mt][nt][1] + b1);
                *(float2*)&out[(size_t)(r + 8) * DM + c] =
                    make_float2(acc[mt][nt][2] + b0, acc[mt][nt][3] + b1);
            }
    }
}

__global__ __launch_bounds__(128) void proj3(float* dummy) {
    if (blockIdx.z == 0)
        gemm16_body(hQ, pWq, nullptr, g_q16, blockIdx.x, blockIdx.y, 0, QSCALE);
    else if (blockIdx.z == 1)
        gemm16_body(hK, pWk, nullptr, g_k16, blockIdx.x, blockIdx.y, 0, 1.f);
    else
        gemm16_body(hV, pWv, nullptr, g_vT, blockIdx.x, blockIdx.y, 1, 1.f);
}

__global__ __launch_bounds__(128) void outg(const float* bias, float* out) {
    gemm16_body(g_a16, pWo, bias, out, blockIdx.x, blockIdx.y, 2, 1.f);
}

// ---------------------------------------------------------------------------
// Flash attention fp16: 64 q-rows x 1 head, 128 thr (4 warps x 16 rows),
// 3 blocks/SM. B-fragments via ldmatrix.m8n8.x4 (2 n-tiles per instr,
// conflict-free at stride 36). Log2 softmax, ex2.f16x2, ones-mma sums.
// ---------------------------------------------------------------------------
#define KT_ST 36
#define ABUF  (2 * 64 * KT_ST)

__global__ __launch_bounds__(128, 3) void attn16(float* dummy)
{
    __shared__ uint32_t sm[2 * ABUF];   // 36864 B
    const uint32_t sb = (uint32_t)__cvta_generic_to_shared(sm);

    const int h = blockIdx.y;
    const int t = blockIdx.x;
    const int iq = (t & 1) ? (63 - (t >> 1)) : (t >> 1);  // heavy/light interleave
    const int tid = threadIdx.x, warp = tid >> 5, lane = tid & 31;
    const int g = lane >> 2, tg = lane & 3;
    const int hoff = h * HD;
    const int qrow0 = iq * 64 + warp * 16 + g;   // rows qrow0, qrow0+8

    // ldmatrix lane offset (bytes): matrices (nt-pair half): m = lane>>3,
    // nt_off = m>>1 -> +8 rows; half = m&1 -> +4 words; r = lane&7.
    const uint32_t lm_ofs =
        (uint32_t)(((lane >> 4) * 8 + (lane & 7)) * KT_ST + ((lane >> 3) & 1) * 4) * 4;

    // Q fragments from gmem fp16 (pre-scaled by QSCALE)
    const uint32_t* qw = (const uint32_t*)g_q16;
    uint32_t qf[4][4];
    {
        size_t b0 = ((size_t)qrow0 * DM + hoff) >> 1;
        size_t b1 = ((size_t)(qrow0 + 8) * DM + hoff) >> 1;
#pragma unroll
        for (int c = 0; c < 4; c++) {
            qf[c][0] = qw[b0 + c * 8 + tg];
            qf[c][1] = qw[b1 + c * 8 + tg];
            qf[c][2] = qw[b0 + c * 8 + tg + 4];
            qf[c][3] = qw[b1 + c * 8 + tg + 4];
        }
    }

    float of[8][4];
#pragma unroll
    for (int nt = 0; nt < 8; nt++)
#pragma unroll
        for (int c = 0; c < 4; c++) of[nt][c] = 0.f;
    float m0r = -1e30f, m1r = -1e30f, l0 = 0.f, l1 = 0.f;

    auto issue = [&](int kt, int b) {
        uint32_t base = sb + (uint32_t)(b * ABUF) * 4;
#pragma unroll
        for (int it = 0; it < 4; it++) {
            int idx = it * 128 + tid;
            int r = idx >> 3, c16 = idx & 7;
            cp16(base + (uint32_t)(r * KT_ST + c16 * 4) * 4,
                 &g_k16[(size_t)(kt * 64 + r) * DM + hoff + c16 * 8]);
            cp16(base + (uint32_t)(64 * KT_ST + r * KT_ST + c16 * 4) * 4,
                 &g_vT[(size_t)(hoff + r) * S_LEN + kt * 64 + c16 * 8]);
        }
        CP_COMMIT();
    };

    issue(0, 0);

    const int ktmax = iq;
    for (int kt = 0; kt <= ktmax; kt++) {
        CP_WAIT_ALL();
        __syncthreads();
        if (kt < ktmax) issue(kt + 1, (kt + 1) & 1);

        const uint32_t Kbase = sb + (uint32_t)((kt & 1) * ABUF) * 4 + lm_ofs;
        const uint32_t Vbase = Kbase + (uint32_t)(64 * KT_ST) * 4;

        // S = Q @ K^T (log2-domain), B-frags via ldmatrix x4 (2 nt per instr)
        float s[8][4];
#pragma unroll
        for (int nt = 0; nt < 8; nt++)
#pragma unroll
            for (int c = 0; c < 4; c++) s[nt][c] = 0.f;

#pragma unroll
        for (int c = 0; c < 4; c++) {
#pragma unroll
            for (int ntp = 0; ntp < 4; ntp++) {
                uint32_t b0a, b1a, b0b, b1b;
                ldsm4(b0a, b1a, b0b, b1b,
                      Kbase + (uint32_t)(ntp * 16 * KT_ST + c * 8) * 4);
                mma_f16(s[2 * ntp],     qf[c][0], qf[c][1], qf[c][2], qf[c][3], b0a, b1a);
                mma_f16(s[2 * ntp + 1], qf[c][0], qf[c][1], qf[c][2], qf[c][3], b0b, b1b);
            }
        }

        // causal mask only on the diagonal tile
        if (kt == iq) {
#pragma unroll
            for (int nt = 0; nt < 8; nt++) {
                int col = kt * 64 + nt * 8 + 2 * tg;
                if (col     > qrow0)     s[nt][0] = -1e30f;
                if (col + 1 > qrow0)     s[nt][1] = -1e30f;
                if (col     > qrow0 + 8) s[nt][2] = -1e30f;
                if (col + 1 > qrow0 + 8) s[nt][3] = -1e30f;
            }
        }

        // online softmax: max + rescale
        float rm0 = -1e30f, rm1 = -1e30f;
#pragma unroll
        for (int nt = 0; nt < 8; nt++) {
            rm0 = fmaxf(rm0, fmaxf(s[nt][0], s[nt][1]));
            rm1 = fmaxf(rm1, fmaxf(s[nt][2], s[nt][3]));
        }
#pragma unroll
        for (int off = 1; off <= 2; off <<= 1) {
            rm0 = fmaxf(rm0, __shfl_xor_sync(0xFFFFFFFFu, rm0, off));
            rm1 = fmaxf(rm1, __shfl_xor_sync(0xFFFFFFFFu, rm1, off));
        }
        float nm0 = fmaxf(m0r, rm0), nm1 = fmaxf(m1r, rm1);
        float al0 = exp2f(m0r - nm0), al1 = exp2f(m1r - nm1);
        m0r = nm0;  m1r = nm1;
        l0 *= al0;  l1 *= al1;
#pragma unroll
        for (int nt = 0; nt < 8; nt++) {
            of[nt][0] *= al0; of[nt][1] *= al0;
            of[nt][2] *= al1; of[nt][3] *= al1;
        }

        // exp in fp16 pairs -> PV A-fragments directly
        uint32_t ah[4][4];
        uint32_t nm0p = f2h2(nm0, nm0), nm1p = f2h2(nm1, nm1);
#pragma unroll
        for (int c = 0; c < 4; c++) {
            ah[c][0] = ex2h2(hsub2u(f2h2(s[2*c][0],   s[2*c][1]),   nm0p));
            ah[c][1] = ex2h2(hsub2u(f2h2(s[2*c][2],   s[2*c][3]),   nm1p));
            ah[c][2] = ex2h2(hsub2u(f2h2(s[2*c+1][0], s[2*c+1][1]), nm0p));
            ah[c][3] = ex2h2(hsub2u(f2h2(s[2*c+1][2], s[2*c+1][3]), nm1p));
        }

        // O += P @ V (ldmatrix B-frags), plus row-sums via ones-mma
        float sacc[4] = {0.f, 0.f, 0.f, 0.f};
#pragma unroll
        for (int c = 0; c < 4; c++) {
#pragma unroll
            for (int ntp = 0; ntp < 4; ntp++) {
                uint32_t b0a, b1a, b0b, b1b;
                ldsm4(b0a, b1a, b0b, b1b,
                      Vbase + (uint32_t)(ntp * 16 * KT_ST + c * 8) * 4);
                mma_f16(of[2 * ntp],     ah[c][0], ah[c][1], ah[c][2], ah[c][3], b0a, b1a);
                mma_f16(of[2 * ntp + 1], ah[c][0], ah[c][1], ah[c][2], ah[c][3], b0b, b1b);
            }
            mma_f16(sacc, ah[c][0], ah[c][1], ah[c][2], ah[c][3], ONESH2, ONESH2);
        }
        l0 += sacc[0];
        l1 += sacc[2];
    }

    // epilogue -> fp16 att buffer
    uint32_t* out = (uint32_t*)g_a16;
    float inv0 = 1.f / l0, inv1 = 1.f / l1;
#pragma unroll
    for (int nt = 0; nt < 8; nt++) {
        int c = hoff + nt * 8 + 2 * tg;
        out[((size_t)qrow0 * DM + c) >> 1] =
            f2h2(of[nt][0] * inv0, of[nt][1] * inv0);
        out[((size_t)(qrow0 + 8) * DM + c) >> 1] =
            f2h2(of[nt][2] * inv1, of[nt][3] * inv1);
    }
}

// ---------------------------------------------------------------------------
// Launch
// ---------------------------------------------------------------------------
extern "C" void kernel_launch(void* const* d_in, const int* in_sizes, int n_in,
                              void* d_out, int out_size)
{
    const float* Q  = (const float*)d_in[0];
    const float* K  = (const float*)d_in[1];
    const float* V  = (const float*)d_in[2];
    const float* Wq = (const float*)d_in[3];
    const float* Wk = (const float*)d_in[4];
    const float* Wv = (const float*)d_in[5];
    const float* Wo = (const float*)d_in[6];
    const float* bo = (const float*)d_in[7];
    float* out = (float*)d_out;

    static bool attr_set = false;
    if (!attr_set) {
        cudaFuncSetAttribute(proj3, cudaFuncAttributeMaxDynamicSharedMemorySize,
                             GEMM_SMEM);
        cudaFuncSetAttribute(outg, cudaFuncAttributeMaxDynamicSharedMemorySize,
                             GEMM_SMEM);
        attr_set = true;
    }

    cvt3<<<dim3(S_LEN * DM / 8 / 256, 3), 256>>>(Q, K, V);
    packw<<<dim3(KW * DM / 256, 4), 256>>>(Wq, Wk, Wv, Wo);

    proj3<<<dim3(DM / 64, S_LEN / 256, 3), 128, GEMM_SMEM>>>(nullptr);

    attn16<<<dim3(S_LEN / 64, NH), 128>>>(nullptr);

    outg<<<dim3(DM / 64, S_LEN / 256), 128, GEMM_SMEM>>>(bo, out);
}